// round 1
// baseline (speedup 1.0000x reference)
#include <cuda_runtime.h>
#include <math.h>

// Problem constants
#define NBATCH 128
#define LTOK   196         // 197 tokens minus CLS
#define CDIM   768
#define KCODES 4096
#define MROWS  (NBATCH * LTOK)   // 25088

#define INV_DELTA_EFF 30.0f      // 15.0 / 0.5
#define NORM_EPS 1e-5f

// Scratch (no allocations allowed; __device__ globals per harness rules)
__device__ float g_invnorm[MROWS];
__device__ float g_rowsum[MROWS];

// ---------------------------------------------------------------------------
// Kernel 1: per-row inverse L2 norm of x[:,1:,:]; zero rowsum for this replay.
// One warp per row.
// ---------------------------------------------------------------------------
__global__ void prep_kernel(const float* __restrict__ x) {
    int gwarp = (blockIdx.x * blockDim.x + threadIdx.x) >> 5;
    int lane  = threadIdx.x & 31;
    if (gwarp >= MROWS) return;
    int n = gwarp / LTOK;
    int l = gwarp % LTOK;
    const float4* row = (const float4*)(x + ((size_t)n * 197 + (l + 1)) * CDIM);
    float s = 0.0f;
#pragma unroll 6
    for (int i = lane; i < CDIM / 4; i += 32) {
        float4 v = row[i];
        s += v.x * v.x + v.y * v.y + v.z * v.z + v.w * v.w;
    }
#pragma unroll
    for (int o = 16; o > 0; o >>= 1) s += __shfl_down_sync(0xffffffffu, s, o);
    if (lane == 0) {
        g_invnorm[gwarp] = 1.0f / fmaxf(sqrtf(s), NORM_EPS);
        g_rowsum[gwarp]  = 0.0f;
    }
}

// ---------------------------------------------------------------------------
// Kernel 2: tiled NT-GEMM  logits = 30 * (xn . emb^T) , fused exp(logit - 30),
// writes unnormalized exp to codes, accumulates row sums via atomics.
// Tile: BM=64, BN=64, BK=16, 256 threads, 4x4 micro-tile per thread.
// ---------------------------------------------------------------------------
#define BM 64
#define BN 64
#define BK 16

__global__ __launch_bounds__(256) void gemm_exp_kernel(
    const float* __restrict__ x,
    const float* __restrict__ emb,
    float* __restrict__ codes)
{
    __shared__ float As[BK][BM];
    __shared__ float Bs[BK][BN];

    const int bn = blockIdx.x;      // 0..63   (KCODES/BN)
    const int bm = blockIdx.y;      // 0..391  (MROWS/BM)
    const int tid = threadIdx.x;
    const int tx = tid & 15;        // column group
    const int ty = tid >> 4;        // row group

    const int row0 = bm * BM;
    const int col0 = bn * BN;

    // Global-load assignment: each thread loads one float4 of A and one of B
    // per BK tile. 64 rows x 4 float4-chunks (BK=16 -> 4 chunks).
    const int lrow = tid >> 2;      // 0..63
    const int lk4  = tid & 3;       // 0..3

    // A source row (fixed across k loop)
    const int arow = row0 + lrow;
    const int an = arow / LTOK;
    const int al = arow % LTOK;
    const float* aptr = x + ((size_t)an * 197 + (al + 1)) * CDIM + lk4 * 4;
    const float ascale = g_invnorm[arow];
    // B source row
    const float* bptr = emb + (size_t)(col0 + lrow) * CDIM + lk4 * 4;

    float acc[4][4] = {};

    for (int k0 = 0; k0 < CDIM; k0 += BK) {
        float4 av = *(const float4*)(aptr + k0);
        float4 bv = *(const float4*)(bptr + k0);
        As[lk4 * 4 + 0][lrow] = av.x * ascale;
        As[lk4 * 4 + 1][lrow] = av.y * ascale;
        As[lk4 * 4 + 2][lrow] = av.z * ascale;
        As[lk4 * 4 + 3][lrow] = av.w * ascale;
        Bs[lk4 * 4 + 0][lrow] = bv.x;
        Bs[lk4 * 4 + 1][lrow] = bv.y;
        Bs[lk4 * 4 + 2][lrow] = bv.z;
        Bs[lk4 * 4 + 3][lrow] = bv.w;
        __syncthreads();

#pragma unroll
        for (int k = 0; k < BK; ++k) {
            float4 a4 = *(const float4*)&As[k][ty * 4];
            float4 b4 = *(const float4*)&Bs[k][tx * 4];
            float a[4] = {a4.x, a4.y, a4.z, a4.w};
            float b[4] = {b4.x, b4.y, b4.z, b4.w};
#pragma unroll
            for (int i = 0; i < 4; ++i)
#pragma unroll
                for (int j = 0; j < 4; ++j)
                    acc[i][j] = fmaf(a[i], b[j], acc[i][j]);
        }
        __syncthreads();
    }

    // Epilogue: p = exp(30*dot - 30); write unnormalized; accumulate row sums.
    float rs[4];
#pragma unroll
    for (int i = 0; i < 4; ++i) {
        float4 p;
        p.x = __expf(fmaf(INV_DELTA_EFF, acc[i][0], -INV_DELTA_EFF));
        p.y = __expf(fmaf(INV_DELTA_EFF, acc[i][1], -INV_DELTA_EFF));
        p.z = __expf(fmaf(INV_DELTA_EFF, acc[i][2], -INV_DELTA_EFF));
        p.w = __expf(fmaf(INV_DELTA_EFF, acc[i][3], -INV_DELTA_EFF));
        size_t r = (size_t)(row0 + ty * 4 + i);
        *(float4*)(codes + r * KCODES + col0 + tx * 4) = p;
        rs[i] = p.x + p.y + p.z + p.w;
    }
    // Reduce rs across the 16 tx lanes (half-warp), then one atomic per row.
#pragma unroll
    for (int i = 0; i < 4; ++i) {
#pragma unroll
        for (int o = 8; o > 0; o >>= 1)
            rs[i] += __shfl_down_sync(0xffffffffu, rs[i], o, 16);
        if (tx == 0)
            atomicAdd(&g_rowsum[row0 + ty * 4 + i], rs[i]);
    }
}

// ---------------------------------------------------------------------------
// Kernel 3: codes *= 1/rowsum  (softmax normalization), float4 elementwise.
// ---------------------------------------------------------------------------
__global__ void scale_kernel(float* __restrict__ codes) {
    size_t i = (size_t)blockIdx.x * blockDim.x + threadIdx.x;  // float4 index
    size_t r = i / (KCODES / 4);
    float inv = 1.0f / g_rowsum[r];
    float4 v = ((float4*)codes)[i];
    v.x *= inv; v.y *= inv; v.z *= inv; v.w *= inv;
    ((float4*)codes)[i] = v;
}

// ---------------------------------------------------------------------------
// Kernel 4: bow[n] = L1-normalized mean of codes over kept tokens
// (grid[2:12, 2:12] of the 14x14 grid -> 100 tokens). One block per batch n.
// ---------------------------------------------------------------------------
__global__ __launch_bounds__(256) void bow_kernel(
    const float* __restrict__ codes, float* __restrict__ bow)
{
    const int n = blockIdx.x;
    const int tid = threadIdx.x;
    float acc[16] = {};  // 4096 / 256 = 16 k-values per thread

#pragma unroll 1
    for (int i = 0; i < 100; ++i) {
        int rr = 2 + i / 10;
        int cc = 2 + i % 10;
        int l  = rr * 14 + cc;
        const float* p = codes + ((size_t)n * LTOK + l) * KCODES;
#pragma unroll
        for (int j = 0; j < 16; ++j)
            acc[j] += p[tid + j * 256];
    }

    float tot = 0.0f;
#pragma unroll
    for (int j = 0; j < 16; ++j) {
        acc[j] *= 0.01f;        // mean over 100 tokens
        tot += acc[j];
    }
    // Block reduction of tot
    __shared__ float sred[256];
    sred[tid] = tot;
    __syncthreads();
    for (int s = 128; s > 0; s >>= 1) {
        if (tid < s) sred[tid] += sred[tid + s];
        __syncthreads();
    }
    float inv = 1.0f / fmaxf(sred[0], NORM_EPS);
#pragma unroll
    for (int j = 0; j < 16; ++j)
        bow[(size_t)n * KCODES + tid + j * 256] = acc[j] * inv;
}

// ---------------------------------------------------------------------------
// Launch
// ---------------------------------------------------------------------------
extern "C" void kernel_launch(void* const* d_in, const int* in_sizes, int n_in,
                              void* d_out, int out_size) {
    const float* x   = (const float*)d_in[0];      // (128, 197, 768)
    const float* emb = (const float*)d_in[1];      // (4096, 768)
    float* out_bow   = (float*)d_out;                       // (128, 4096)
    float* out_codes = (float*)d_out + (size_t)NBATCH * KCODES;  // (128,196,4096)

    // 1. row norms + rowsum zeroing: one warp per row
    {
        int warps = MROWS;
        int threads = 256;
        int blocks = (warps * 32 + threads - 1) / threads;
        prep_kernel<<<blocks, threads>>>(x);
    }
    // 2. GEMM + exp
    {
        dim3 grid(KCODES / BN, MROWS / BM);   // (64, 392)
        gemm_exp_kernel<<<grid, 256>>>(x, emb, out_codes);
    }
    // 3. softmax normalize
    {
        size_t nf4 = (size_t)MROWS * KCODES / 4;   // 25,690,112
        int threads = 256;
        int blocks = (int)(nf4 / threads);         // divides exactly: 100352
        scale_kernel<<<blocks, threads>>>(out_codes);
    }
    // 4. bow
    bow_kernel<<<NBATCH, 256>>>(out_codes, out_bow);
}

// round 3
// speedup vs baseline: 1.6779x; 1.6779x over previous
#include <cuda_runtime.h>
#include <cuda_fp16.h>
#include <cstdint>
#include <math.h>

// ---------------------------------------------------------------------------
// Problem constants
// ---------------------------------------------------------------------------
#define NBATCH 128
#define LTOK   196
#define CDIM   768
#define KCODES 4096
#define MROWS  (NBATCH * LTOK)        // 25088
#define INV_DELTA_EFF 30.0f           // 15.0 / 0.5
#define NORM_EPS 1e-5f

// GEMM tiling (HMMA mma.sync path; tcgen05 is unavailable: harness compiles
// through compute_103 virtual arch which rejects sm_103a-only instructions)
#define BM 256
#define BN 256
#define BK 32
#define NCHUNK (CDIM / BK)            // 24
#define GTHREADS 512                  // 16 warps: 4x4, warp tile 64x64

// smem: padded rows: 32 halves data + 8 pad = 40 halves = 80 B per row
#define ROWB 80
#define BUF_BYTES (256 * ROWB)        // 20480 per operand buffer
#define STAGE_BYTES (4 * BUF_BYTES)   // Ah, Al, Bh, Bl = 81920
#define SMEM_GEMM (2 * STAGE_BYTES)   // 163840

// ---------------------------------------------------------------------------
// Scratch (__device__ globals; no allocations allowed)
// ---------------------------------------------------------------------------
__device__ __half g_Ahi[(size_t)MROWS * CDIM];
__device__ __half g_Alo[(size_t)MROWS * CDIM];
__device__ __half g_Bhi[(size_t)KCODES * CDIM];
__device__ __half g_Blo[(size_t)KCODES * CDIM];
__device__ float  g_rowsum[MROWS];

// ---------------------------------------------------------------------------
// PTX helpers (portable: cp.async sm_80+, ldmatrix sm_75+, mma.sync sm_80+)
// ---------------------------------------------------------------------------
__device__ __forceinline__ uint32_t smem_u32(const void* p) {
    uint32_t a;
    asm("{ .reg .u64 t; cvta.to.shared.u64 t, %1; cvt.u32.u64 %0, t; }" : "=r"(a) : "l"(p));
    return a;
}
#define CP_ASYNC16(dst, src) \
    asm volatile("cp.async.cg.shared.global [%0], [%1], 16;\n" :: "r"(dst), "l"(src))
#define CP_COMMIT() asm volatile("cp.async.commit_group;\n" ::: "memory")
#define CP_WAIT1()  asm volatile("cp.async.wait_group 1;\n" ::: "memory")
#define CP_WAIT0()  asm volatile("cp.async.wait_group 0;\n" ::: "memory")

__device__ __forceinline__ void ldsm_x4(uint32_t* r, uint32_t addr) {
    asm volatile("ldmatrix.sync.aligned.m8n8.x4.shared.b16 {%0,%1,%2,%3}, [%4];"
                 : "=r"(r[0]), "=r"(r[1]), "=r"(r[2]), "=r"(r[3]) : "r"(addr));
}
__device__ __forceinline__ void mma16816(float* c, const uint32_t* a, uint32_t b0, uint32_t b1) {
    asm volatile("mma.sync.aligned.m16n8k16.row.col.f32.f16.f16.f32 "
                 "{%0,%1,%2,%3}, {%4,%5,%6,%7}, {%8,%9}, {%0,%1,%2,%3};"
                 : "+f"(c[0]), "+f"(c[1]), "+f"(c[2]), "+f"(c[3])
                 : "r"(a[0]), "r"(a[1]), "r"(a[2]), "r"(a[3]), "r"(b0), "r"(b1));
}

// ---------------------------------------------------------------------------
// Kernel 1: row inv-L2-norm of x[:,1:,:]; write fp16 hi/lo of xn; zero rowsum.
// One warp per row.
// ---------------------------------------------------------------------------
__global__ void prep_x_kernel(const float* __restrict__ x) {
    int gw = (blockIdx.x * blockDim.x + threadIdx.x) >> 5;
    int lane = threadIdx.x & 31;
    if (gw >= MROWS) return;
    int n = gw / LTOK, l = gw % LTOK;
    const float4* r4 = (const float4*)(x + ((size_t)n * 197 + l + 1) * CDIM);

    float4 v[6];
    float s = 0.0f;
#pragma unroll
    for (int i = 0; i < 6; ++i) {
        v[i] = r4[lane + i * 32];
        s += v[i].x * v[i].x + v[i].y * v[i].y + v[i].z * v[i].z + v[i].w * v[i].w;
    }
#pragma unroll
    for (int o = 16; o > 0; o >>= 1) s += __shfl_xor_sync(0xffffffffu, s, o);
    float inv = 1.0f / fmaxf(sqrtf(s), NORM_EPS);

    uint2* ah = (uint2*)(g_Ahi + (size_t)gw * CDIM);
    uint2* al = (uint2*)(g_Alo + (size_t)gw * CDIM);
#pragma unroll
    for (int i = 0; i < 6; ++i) {
        float a[4] = {v[i].x * inv, v[i].y * inv, v[i].z * inv, v[i].w * inv};
        __half h[4], lo[4];
#pragma unroll
        for (int c = 0; c < 4; ++c) {
            h[c]  = __float2half_rn(a[c]);
            lo[c] = __float2half_rn(a[c] - __half2float(h[c]));
        }
        int idx = lane + i * 32;   // float4 index -> uint2 index
        ah[idx] = *(uint2*)h;
        al[idx] = *(uint2*)lo;
    }
    if (lane == 0) g_rowsum[gw] = 0.0f;
}

// ---------------------------------------------------------------------------
// Kernel 2: embedding -> fp16 hi/lo. One float4 per thread.
// ---------------------------------------------------------------------------
__global__ void conv_emb_kernel(const float* __restrict__ emb) {
    size_t i = (size_t)blockIdx.x * blockDim.x + threadIdx.x;
    float4 e = ((const float4*)emb)[i];
    float a[4] = {e.x, e.y, e.z, e.w};
    __half h[4], lo[4];
#pragma unroll
    for (int c = 0; c < 4; ++c) {
        h[c]  = __float2half_rn(a[c]);
        lo[c] = __float2half_rn(a[c] - __half2float(h[c]));
    }
    ((uint2*)g_Bhi)[i] = *(uint2*)h;
    ((uint2*)g_Blo)[i] = *(uint2*)lo;
}

// ---------------------------------------------------------------------------
// Kernel 3: HMMA GEMM (fp16 2-term split, 3 MMA products) + fused exp epilogue.
// CTA 256x256, BK=32, 2-stage cp.async pipeline.
// ---------------------------------------------------------------------------
__device__ __forceinline__ void load_stage(uint32_t stage_sb, int k0, int row0, int col0, int tid) {
    const int buf = tid >> 7;              // 0=Ah 1=Al 2=Bh 3=Bl
    const int r2  = (tid & 127) * 2;       // base row (2 rows per thread)
    const __half* gbase;
    int goff;
    switch (buf) {
        case 0:  gbase = g_Ahi; goff = row0; break;
        case 1:  gbase = g_Alo; goff = row0; break;
        case 2:  gbase = g_Bhi; goff = col0; break;
        default: gbase = g_Blo; goff = col0; break;
    }
    uint32_t dbase = stage_sb + buf * BUF_BYTES;
#pragma unroll
    for (int j = 0; j < 8; ++j) {
        int row = r2 + (j >> 2);
        int ch  = j & 3;
        const __half* src = gbase + (size_t)(goff + row) * CDIM + k0 + ch * 8;
        CP_ASYNC16(dbase + row * ROWB + ch * 16, src);
    }
    CP_COMMIT();
}

__global__ __launch_bounds__(GTHREADS, 1) void gemm_exp_kernel(float* __restrict__ codes) {
    extern __shared__ char smem[];
    const uint32_t sb = smem_u32(smem);
    const int tid  = threadIdx.x;
    const int lane = tid & 31;
    const int warp = tid >> 5;
    const int wm = warp >> 2;              // 0..3
    const int wn = warp & 3;               // 0..3
    const int row0 = blockIdx.y * BM;
    const int col0 = blockIdx.x * BN;

    const int lm = lane & 7;
    const int lg = lane >> 3;              // ldmatrix matrix index

    // ldmatrix address components (bytes within a buffer)
    // A: matrix order (m0-7,k0-7),(m8-15,k0-7),(m0-7,k8-15),(m8-15,k8-15)
    const int a_row = wm * 64 + lm + (lg & 1) * 8;      // + mf*16
    const int a_kk  = (lg >> 1) * 8;
    // B: matrix order (n0-7,k0-7),(n0-7,k8-15),(n8-15,k0-7),(n8-15,k8-15)
    const int b_row = wn * 64 + lm + (lg >> 1) * 8;     // + nf2*16
    const int b_kk  = (lg & 1) * 8;

    float acc[4][8][4];
#pragma unroll
    for (int i = 0; i < 4; ++i)
#pragma unroll
        for (int j = 0; j < 8; ++j)
#pragma unroll
            for (int c = 0; c < 4; ++c) acc[i][j][c] = 0.0f;

    load_stage(sb, 0, row0, col0, tid);
    load_stage(sb + STAGE_BYTES, BK, row0, col0, tid);

    for (int i = 0; i < NCHUNK; ++i) {
        if (i < NCHUNK - 1) { CP_WAIT1(); } else { CP_WAIT0(); }
        __syncthreads();

        const uint32_t sA = sb + (i & 1) * STAGE_BYTES;
        const uint32_t sB = sA + 2 * BUF_BYTES;

#pragma unroll
        for (int ks = 0; ks < 2; ++ks) {
            uint32_t aH[4][4], aL[4][4];
#pragma unroll
            for (int mf = 0; mf < 4; ++mf) {
                uint32_t aoff = (uint32_t)((a_row + mf * 16) * ROWB + (ks * 16 + a_kk) * 2);
                ldsm_x4(aH[mf], sA + aoff);
                ldsm_x4(aL[mf], sA + BUF_BYTES + aoff);
            }
#pragma unroll
            for (int nf2 = 0; nf2 < 4; ++nf2) {
                uint32_t bH[4], bL[4];
                uint32_t boff = (uint32_t)((b_row + nf2 * 16) * ROWB + (ks * 16 + b_kk) * 2);
                ldsm_x4(bH, sB + boff);
                ldsm_x4(bL, sB + BUF_BYTES + boff);
#pragma unroll
                for (int mf = 0; mf < 4; ++mf) {
                    mma16816(acc[mf][nf2 * 2 + 0], aH[mf], bH[0], bH[1]);
                    mma16816(acc[mf][nf2 * 2 + 1], aH[mf], bH[2], bH[3]);
                    mma16816(acc[mf][nf2 * 2 + 0], aH[mf], bL[0], bL[1]);
                    mma16816(acc[mf][nf2 * 2 + 1], aH[mf], bL[2], bL[3]);
                    mma16816(acc[mf][nf2 * 2 + 0], aL[mf], bH[0], bH[1]);
                    mma16816(acc[mf][nf2 * 2 + 1], aL[mf], bH[2], bH[3]);
                }
            }
        }

        __syncthreads();
        if (i + 2 < NCHUNK)
            load_stage(sb + (i & 1) * STAGE_BYTES, (i + 2) * BK, row0, col0, tid);
    }

    // Epilogue: p = exp(30*d - 30); coalesced v2 stores; rowsum atomics.
#pragma unroll
    for (int mf = 0; mf < 4; ++mf) {
        int gr = row0 + wm * 64 + mf * 16 + (lane >> 2);   // rows gr and gr+8
        float s0 = 0.0f, s1 = 0.0f;
#pragma unroll
        for (int nf = 0; nf < 8; ++nf) {
            float* c = acc[mf][nf];
            float2 p0, p1;
            p0.x = __expf(fmaf(INV_DELTA_EFF, c[0], -INV_DELTA_EFF));
            p0.y = __expf(fmaf(INV_DELTA_EFF, c[1], -INV_DELTA_EFF));
            p1.x = __expf(fmaf(INV_DELTA_EFF, c[2], -INV_DELTA_EFF));
            p1.y = __expf(fmaf(INV_DELTA_EFF, c[3], -INV_DELTA_EFF));
            int gc = col0 + wn * 64 + nf * 8 + (lane & 3) * 2;
            *(float2*)(codes + (size_t)gr * KCODES + gc)       = p0;
            *(float2*)(codes + (size_t)(gr + 8) * KCODES + gc) = p1;
            s0 += p0.x + p0.y;
            s1 += p1.x + p1.y;
        }
        s0 += __shfl_xor_sync(0xffffffffu, s0, 1);
        s0 += __shfl_xor_sync(0xffffffffu, s0, 2);
        s1 += __shfl_xor_sync(0xffffffffu, s1, 1);
        s1 += __shfl_xor_sync(0xffffffffu, s1, 2);
        if ((lane & 3) == 0) {
            atomicAdd(&g_rowsum[gr], s0);
            atomicAdd(&g_rowsum[gr + 8], s1);
        }
    }
}

// ---------------------------------------------------------------------------
// Kernel 4: softmax normalize codes (float4 elementwise)
// ---------------------------------------------------------------------------
__global__ void scale_kernel(float* __restrict__ codes) {
    size_t i = (size_t)blockIdx.x * blockDim.x + threadIdx.x;   // float4 index
    size_t r = i >> 10;                                         // / (4096/4)
    float inv = 1.0f / g_rowsum[r];
    float4 v = ((float4*)codes)[i];
    v.x *= inv; v.y *= inv; v.z *= inv; v.w *= inv;
    ((float4*)codes)[i] = v;
}

// ---------------------------------------------------------------------------
// Kernel 5a: bow partial means. grid (128, 16), 64 threads.
// ---------------------------------------------------------------------------
__global__ __launch_bounds__(64) void bow_partial_kernel(
    const float* __restrict__ codes, float* __restrict__ bow)
{
    int n = blockIdx.x, kc = blockIdx.y, t = threadIdx.x;
    int col = kc * 256 + t * 4;
    float4 acc = make_float4(0.f, 0.f, 0.f, 0.f);
#pragma unroll 1
    for (int rr = 2; rr < 12; ++rr) {
#pragma unroll
        for (int cc = 2; cc < 12; ++cc) {
            int l = rr * 14 + cc;
            float4 v = *(const float4*)(codes + ((size_t)n * LTOK + l) * KCODES + col);
            acc.x += v.x; acc.y += v.y; acc.z += v.z; acc.w += v.w;
        }
    }
    acc.x *= 0.01f; acc.y *= 0.01f; acc.z *= 0.01f; acc.w *= 0.01f;
    *(float4*)(bow + (size_t)n * KCODES + col) = acc;
}

// ---------------------------------------------------------------------------
// Kernel 5b: L1-normalize bow rows.
// ---------------------------------------------------------------------------
__global__ __launch_bounds__(256) void bow_norm_kernel(float* __restrict__ bow) {
    int n = blockIdx.x, t = threadIdx.x;
    float4* row = (float4*)(bow + (size_t)n * KCODES);
    float4 v[4];
    float s = 0.0f;
#pragma unroll
    for (int j = 0; j < 4; ++j) {
        v[j] = row[t + j * 256];
        s += fabsf(v[j].x) + fabsf(v[j].y) + fabsf(v[j].z) + fabsf(v[j].w);
    }
    __shared__ float sred[256];
    sred[t] = s;
    __syncthreads();
    for (int o = 128; o > 0; o >>= 1) {
        if (t < o) sred[t] += sred[t + o];
        __syncthreads();
    }
    float inv = 1.0f / fmaxf(sred[0], NORM_EPS);
#pragma unroll
    for (int j = 0; j < 4; ++j) {
        v[j].x *= inv; v[j].y *= inv; v[j].z *= inv; v[j].w *= inv;
        row[t + j * 256] = v[j];
    }
}

// ---------------------------------------------------------------------------
// Launch
// ---------------------------------------------------------------------------
extern "C" void kernel_launch(void* const* d_in, const int* in_sizes, int n_in,
                              void* d_out, int out_size) {
    const float* x   = (const float*)d_in[0];
    const float* emb = (const float*)d_in[1];
    float* out_bow   = (float*)d_out;
    float* out_codes = (float*)d_out + (size_t)NBATCH * KCODES;

    cudaFuncSetAttribute(gemm_exp_kernel, cudaFuncAttributeMaxDynamicSharedMemorySize,
                         SMEM_GEMM);

    prep_x_kernel<<<MROWS * 32 / 256, 256>>>(x);
    conv_emb_kernel<<<(KCODES * CDIM / 4) / 256, 256>>>(emb);

    gemm_exp_kernel<<<dim3(KCODES / BN, MROWS / BM), GTHREADS, SMEM_GEMM>>>(out_codes);

    {
        size_t nf4 = (size_t)MROWS * KCODES / 4;
        scale_kernel<<<(int)(nf4 / 256), 256>>>(out_codes);
    }
    bow_partial_kernel<<<dim3(NBATCH, 16), 64>>>(out_codes, out_bow);
    bow_norm_kernel<<<NBATCH, 256>>>(out_bow);
}

// round 4
// speedup vs baseline: 2.5996x; 1.5493x over previous
#include <cuda_runtime.h>
#include <cuda_fp16.h>
#include <cstdint>
#include <math.h>

// ---------------------------------------------------------------------------
// Problem constants
// ---------------------------------------------------------------------------
#define NBATCH 128
#define LTOK   196
#define CDIM   768
#define KCODES 4096
#define MROWS  (NBATCH * LTOK)        // 25088
#define INV_DELTA_EFF 30.0f           // 15.0 / 0.5
#define NORM_EPS 1e-5f

// GEMM tiling (portable HMMA mma.sync path; tcgen05 rejected by compute_103)
#define BM 128
#define BN 256
#define BK 32
#define NCHUNK (CDIM / BK)            // 24
#define GTHREADS 256                  // 8 warps: 2x4, warp tile 64x64
#define NSTAGE 3

// smem rows: 32 halves data + 8 pad = 40 halves = 80 B per row (conflict-free
// for ldmatrix: bank stride 20 words -> 8 rows hit 8 distinct 4-bank groups)
#define ROWB 80
#define ABUF_BYTES (128 * ROWB)       // 10240
#define BBUF_BYTES (256 * ROWB)       // 20480
#define OFF_AHI 0
#define OFF_ALO ABUF_BYTES
#define OFF_BHI (2 * ABUF_BYTES)
#define OFF_BLO (2 * ABUF_BYTES + BBUF_BYTES)
#define STAGE_BYTES (2 * ABUF_BYTES + 2 * BBUF_BYTES)   // 61440
#define SMEM_GEMM (NSTAGE * STAGE_BYTES)                // 184320

// ---------------------------------------------------------------------------
// Scratch (__device__ globals; no allocations allowed)
// ---------------------------------------------------------------------------
__device__ __half g_Ahi[(size_t)MROWS * CDIM];
__device__ __half g_Alo[(size_t)MROWS * CDIM];
__device__ __half g_Bhi[(size_t)KCODES * CDIM];
__device__ __half g_Blo[(size_t)KCODES * CDIM];
__device__ float  g_rowsum[MROWS];

// ---------------------------------------------------------------------------
// PTX helpers (portable: cp.async sm_80+, ldmatrix sm_75+, mma.sync sm_80+)
// ---------------------------------------------------------------------------
__device__ __forceinline__ uint32_t smem_u32(const void* p) {
    uint32_t a;
    asm("{ .reg .u64 t; cvta.to.shared.u64 t, %1; cvt.u32.u64 %0, t; }" : "=r"(a) : "l"(p));
    return a;
}
#define CP_ASYNC16(dst, src) \
    asm volatile("cp.async.cg.shared.global [%0], [%1], 16;\n" :: "r"(dst), "l"(src))
#define CP_COMMIT() asm volatile("cp.async.commit_group;\n" ::: "memory")
#define CP_WAIT2()  asm volatile("cp.async.wait_group 2;\n" ::: "memory")
#define CP_WAIT1()  asm volatile("cp.async.wait_group 1;\n" ::: "memory")
#define CP_WAIT0()  asm volatile("cp.async.wait_group 0;\n" ::: "memory")

__device__ __forceinline__ void ldsm_x4(uint32_t* r, uint32_t addr) {
    asm volatile("ldmatrix.sync.aligned.m8n8.x4.shared.b16 {%0,%1,%2,%3}, [%4];"
                 : "=r"(r[0]), "=r"(r[1]), "=r"(r[2]), "=r"(r[3]) : "r"(addr));
}
__device__ __forceinline__ void mma16816(float* c, const uint32_t* a, uint32_t b0, uint32_t b1) {
    asm volatile("mma.sync.aligned.m16n8k16.row.col.f32.f16.f16.f32 "
                 "{%0,%1,%2,%3}, {%4,%5,%6,%7}, {%8,%9}, {%0,%1,%2,%3};"
                 : "+f"(c[0]), "+f"(c[1]), "+f"(c[2]), "+f"(c[3])
                 : "r"(a[0]), "r"(a[1]), "r"(a[2]), "r"(a[3]), "r"(b0), "r"(b1));
}

// ---------------------------------------------------------------------------
// Kernel 1: row inv-L2-norm of x[:,1:,:]; write fp16 hi/lo of xn; zero rowsum.
// One warp per row.
// ---------------------------------------------------------------------------
__global__ void prep_x_kernel(const float* __restrict__ x) {
    int gw = (blockIdx.x * blockDim.x + threadIdx.x) >> 5;
    int lane = threadIdx.x & 31;
    if (gw >= MROWS) return;
    int n = gw / LTOK, l = gw % LTOK;
    const float4* r4 = (const float4*)(x + ((size_t)n * 197 + l + 1) * CDIM);

    float4 v[6];
    float s = 0.0f;
#pragma unroll
    for (int i = 0; i < 6; ++i) {
        v[i] = r4[lane + i * 32];
        s += v[i].x * v[i].x + v[i].y * v[i].y + v[i].z * v[i].z + v[i].w * v[i].w;
    }
#pragma unroll
    for (int o = 16; o > 0; o >>= 1) s += __shfl_xor_sync(0xffffffffu, s, o);
    float inv = 1.0f / fmaxf(sqrtf(s), NORM_EPS);

    uint2* ah = (uint2*)(g_Ahi + (size_t)gw * CDIM);
    uint2* al = (uint2*)(g_Alo + (size_t)gw * CDIM);
#pragma unroll
    for (int i = 0; i < 6; ++i) {
        float a[4] = {v[i].x * inv, v[i].y * inv, v[i].z * inv, v[i].w * inv};
        __half h[4], lo[4];
#pragma unroll
        for (int c = 0; c < 4; ++c) {
            h[c]  = __float2half_rn(a[c]);
            lo[c] = __float2half_rn(a[c] - __half2float(h[c]));
        }
        int idx = lane + i * 32;
        ah[idx] = *(uint2*)h;
        al[idx] = *(uint2*)lo;
    }
    if (lane == 0) g_rowsum[gw] = 0.0f;
}

// ---------------------------------------------------------------------------
// Kernel 2: embedding -> fp16 hi/lo. One float4 per thread.
// ---------------------------------------------------------------------------
__global__ void conv_emb_kernel(const float* __restrict__ emb) {
    size_t i = (size_t)blockIdx.x * blockDim.x + threadIdx.x;
    float4 e = ((const float4*)emb)[i];
    float a[4] = {e.x, e.y, e.z, e.w};
    __half h[4], lo[4];
#pragma unroll
    for (int c = 0; c < 4; ++c) {
        h[c]  = __float2half_rn(a[c]);
        lo[c] = __float2half_rn(a[c] - __half2float(h[c]));
    }
    ((uint2*)g_Bhi)[i] = *(uint2*)h;
    ((uint2*)g_Blo)[i] = *(uint2*)lo;
}

// ---------------------------------------------------------------------------
// Kernel 3: HMMA GEMM (fp16 2-term split, 3 MMA products) + fused exp epilogue.
// CTA 128x256, BK=32, 256 threads, 3-stage cp.async pipeline. No spills:
// 256 threads -> 255-reg cap, ~190 live.
// ---------------------------------------------------------------------------
__device__ __forceinline__ void load_stage(uint32_t stage_sb, int k0, int row0, int col0, int tid) {
    // A: 2 bufs x 128 rows x 4 chunks = 1024 chunks; 4 per thread
#pragma unroll
    for (int j = 0; j < 4; ++j) {
        int c = tid * 4 + j;
        int buf = c >> 9;                  // 0=Ahi 1=Alo
        int rem = c & 511;
        int row = rem >> 2, ch = rem & 3;
        const __half* src = (buf ? g_Alo : g_Ahi) + (size_t)(row0 + row) * CDIM + k0 + ch * 8;
        CP_ASYNC16(stage_sb + buf * ABUF_BYTES + row * ROWB + ch * 16, src);
    }
    // B: 2 bufs x 256 rows x 4 chunks = 2048 chunks; 8 per thread
#pragma unroll
    for (int j = 0; j < 8; ++j) {
        int c = tid * 8 + j;
        int buf = c >> 10;                 // 0=Bhi 1=Blo
        int rem = c & 1023;
        int row = rem >> 2, ch = rem & 3;
        const __half* src = (buf ? g_Blo : g_Bhi) + (size_t)(col0 + row) * CDIM + k0 + ch * 8;
        CP_ASYNC16(stage_sb + OFF_BHI + buf * BBUF_BYTES + row * ROWB + ch * 16, src);
    }
    CP_COMMIT();
}

__global__ __launch_bounds__(GTHREADS, 1) void gemm_exp_kernel(float* __restrict__ codes) {
    extern __shared__ char smem[];
    const uint32_t sb = smem_u32(smem);
    const int tid  = threadIdx.x;
    const int lane = tid & 31;
    const int warp = tid >> 5;
    const int wm = warp >> 2;              // 0..1
    const int wn = warp & 3;               // 0..3
    const int row0 = blockIdx.y * BM;
    const int col0 = blockIdx.x * BN;

    const int lm = lane & 7;
    const int lg = lane >> 3;

    // Fragment addressing identical to the verified round-3 kernel.
    const int a_row = wm * 64 + lm + (lg & 1) * 8;      // + mf*16
    const int a_kk  = (lg >> 1) * 8;
    const int b_row = wn * 64 + lm + (lg >> 1) * 8;     // + nf2*16
    const int b_kk  = (lg & 1) * 8;

    float acc[4][8][4];
#pragma unroll
    for (int i = 0; i < 4; ++i)
#pragma unroll
        for (int j = 0; j < 8; ++j)
#pragma unroll
            for (int c = 0; c < 4; ++c) acc[i][j][c] = 0.0f;

    load_stage(sb + 0 * STAGE_BYTES, 0 * BK, row0, col0, tid);
    load_stage(sb + 1 * STAGE_BYTES, 1 * BK, row0, col0, tid);
    load_stage(sb + 2 * STAGE_BYTES, 2 * BK, row0, col0, tid);

    for (int i = 0; i < NCHUNK; ++i) {
        if (i < NCHUNK - 2)      { CP_WAIT2(); }
        else if (i == NCHUNK - 2){ CP_WAIT1(); }
        else                     { CP_WAIT0(); }
        __syncthreads();

        const uint32_t sA = sb + (i % NSTAGE) * STAGE_BYTES;
        const uint32_t sB = sA + OFF_BHI;

#pragma unroll
        for (int ks = 0; ks < 2; ++ks) {
            uint32_t aH[4][4], aL[4][4];
#pragma unroll
            for (int mf = 0; mf < 4; ++mf) {
                uint32_t aoff = (uint32_t)((a_row + mf * 16) * ROWB + (ks * 16 + a_kk) * 2);
                ldsm_x4(aH[mf], sA + aoff);
                ldsm_x4(aL[mf], sA + ABUF_BYTES + aoff);
            }
#pragma unroll
            for (int nf2 = 0; nf2 < 4; ++nf2) {
                uint32_t bH[4], bL[4];
                uint32_t boff = (uint32_t)((b_row + nf2 * 16) * ROWB + (ks * 16 + b_kk) * 2);
                ldsm_x4(bH, sB + boff);
                ldsm_x4(bL, sB + BBUF_BYTES + boff);
#pragma unroll
                for (int mf = 0; mf < 4; ++mf) {
                    mma16816(acc[mf][nf2 * 2 + 0], aH[mf], bH[0], bH[1]);
                    mma16816(acc[mf][nf2 * 2 + 1], aH[mf], bH[2], bH[3]);
                    mma16816(acc[mf][nf2 * 2 + 0], aH[mf], bL[0], bL[1]);
                    mma16816(acc[mf][nf2 * 2 + 1], aH[mf], bL[2], bL[3]);
                    mma16816(acc[mf][nf2 * 2 + 0], aL[mf], bH[0], bH[1]);
                    mma16816(acc[mf][nf2 * 2 + 1], aL[mf], bH[2], bH[3]);
                }
            }
        }

        __syncthreads();
        if (i + NSTAGE < NCHUNK)
            load_stage(sb + (i % NSTAGE) * STAGE_BYTES, (i + NSTAGE) * BK, row0, col0, tid);
    }

    // Epilogue: p = exp(30*d - 30); coalesced v2 stores; rowsum atomics.
#pragma unroll
    for (int mf = 0; mf < 4; ++mf) {
        int gr = row0 + wm * 64 + mf * 16 + (lane >> 2);   // rows gr and gr+8
        float s0 = 0.0f, s1 = 0.0f;
#pragma unroll
        for (int nf = 0; nf < 8; ++nf) {
            float* c = acc[mf][nf];
            float2 p0, p1;
            p0.x = __expf(fmaf(INV_DELTA_EFF, c[0], -INV_DELTA_EFF));
            p0.y = __expf(fmaf(INV_DELTA_EFF, c[1], -INV_DELTA_EFF));
            p1.x = __expf(fmaf(INV_DELTA_EFF, c[2], -INV_DELTA_EFF));
            p1.y = __expf(fmaf(INV_DELTA_EFF, c[3], -INV_DELTA_EFF));
            int gc = col0 + wn * 64 + nf * 8 + (lane & 3) * 2;
            *(float2*)(codes + (size_t)gr * KCODES + gc)       = p0;
            *(float2*)(codes + (size_t)(gr + 8) * KCODES + gc) = p1;
            s0 += p0.x + p0.y;
            s1 += p1.x + p1.y;
        }
        s0 += __shfl_xor_sync(0xffffffffu, s0, 1);
        s0 += __shfl_xor_sync(0xffffffffu, s0, 2);
        s1 += __shfl_xor_sync(0xffffffffu, s1, 1);
        s1 += __shfl_xor_sync(0xffffffffu, s1, 2);
        if ((lane & 3) == 0) {
            atomicAdd(&g_rowsum[gr], s0);
            atomicAdd(&g_rowsum[gr + 8], s1);
        }
    }
}

// ---------------------------------------------------------------------------
// Kernel 4: softmax normalize codes (float4 elementwise)
// ---------------------------------------------------------------------------
__global__ void scale_kernel(float* __restrict__ codes) {
    size_t i = (size_t)blockIdx.x * blockDim.x + threadIdx.x;   // float4 index
    size_t r = i >> 10;                                         // / (4096/4)
    float inv = 1.0f / g_rowsum[r];
    float4 v = ((float4*)codes)[i];
    v.x *= inv; v.y *= inv; v.z *= inv; v.w *= inv;
    ((float4*)codes)[i] = v;
}

// ---------------------------------------------------------------------------
// Kernel 5a: bow partial means. grid (128, 16), 64 threads.
// ---------------------------------------------------------------------------
__global__ __launch_bounds__(64) void bow_partial_kernel(
    const float* __restrict__ codes, float* __restrict__ bow)
{
    int n = blockIdx.x, kc = blockIdx.y, t = threadIdx.x;
    int col = kc * 256 + t * 4;
    float4 acc = make_float4(0.f, 0.f, 0.f, 0.f);
#pragma unroll 1
    for (int rr = 2; rr < 12; ++rr) {
#pragma unroll
        for (int cc = 2; cc < 12; ++cc) {
            int l = rr * 14 + cc;
            float4 v = *(const float4*)(codes + ((size_t)n * LTOK + l) * KCODES + col);
            acc.x += v.x; acc.y += v.y; acc.z += v.z; acc.w += v.w;
        }
    }
    acc.x *= 0.01f; acc.y *= 0.01f; acc.z *= 0.01f; acc.w *= 0.01f;
    *(float4*)(bow + (size_t)n * KCODES + col) = acc;
}

// ---------------------------------------------------------------------------
// Kernel 5b: L1-normalize bow rows.
// ---------------------------------------------------------------------------
__global__ __launch_bounds__(256) void bow_norm_kernel(float* __restrict__ bow) {
    int n = blockIdx.x, t = threadIdx.x;
    float4* row = (float4*)(bow + (size_t)n * KCODES);
    float4 v[4];
    float s = 0.0f;
#pragma unroll
    for (int j = 0; j < 4; ++j) {
        v[j] = row[t + j * 256];
        s += fabsf(v[j].x) + fabsf(v[j].y) + fabsf(v[j].z) + fabsf(v[j].w);
    }
    __shared__ float sred[256];
    sred[t] = s;
    __syncthreads();
    for (int o = 128; o > 0; o >>= 1) {
        if (t < o) sred[t] += sred[t + o];
        __syncthreads();
    }
    float inv = 1.0f / fmaxf(sred[0], NORM_EPS);
#pragma unroll
    for (int j = 0; j < 4; ++j) {
        v[j].x *= inv; v[j].y *= inv; v[j].z *= inv; v[j].w *= inv;
        row[t + j * 256] = v[j];
    }
}

// ---------------------------------------------------------------------------
// Launch
// ---------------------------------------------------------------------------
extern "C" void kernel_launch(void* const* d_in, const int* in_sizes, int n_in,
                              void* d_out, int out_size) {
    const float* x   = (const float*)d_in[0];
    const float* emb = (const float*)d_in[1];
    float* out_bow   = (float*)d_out;
    float* out_codes = (float*)d_out + (size_t)NBATCH * KCODES;

    cudaFuncSetAttribute(gemm_exp_kernel, cudaFuncAttributeMaxDynamicSharedMemorySize,
                         SMEM_GEMM);

    prep_x_kernel<<<MROWS * 32 / 256, 256>>>(x);
    conv_emb_kernel<<<(KCODES * CDIM / 4) / 256, 256>>>(emb);

    gemm_exp_kernel<<<dim3(KCODES / BN, MROWS / BM), GTHREADS, SMEM_GEMM>>>(out_codes);

    {
        size_t nf4 = (size_t)MROWS * KCODES / 4;
        scale_kernel<<<(int)(nf4 / 256), 256>>>(out_codes);
    }
    bow_partial_kernel<<<dim3(NBATCH, 16), 64>>>(out_codes, out_bow);
    bow_norm_kernel<<<NBATCH, 256>>>(out_bow);
}

// round 5
// speedup vs baseline: 2.7223x; 1.0472x over previous
#include <cuda_runtime.h>
#include <cuda_fp16.h>
#include <cstdint>
#include <math.h>

// ---------------------------------------------------------------------------
// Problem constants
// ---------------------------------------------------------------------------
#define NBATCH 128
#define LTOK   196
#define CDIM   768
#define KCODES 4096
#define MROWS  (NBATCH * LTOK)        // 25088
#define INV_DELTA_EFF 30.0f           // 15.0 / 0.5
#define NORM_EPS 1e-5f

// GEMM tiling (portable HMMA mma.sync path)
#define BM 128
#define BN 256
#define BK 32
#define NCHUNK (CDIM / BK)            // 24
#define GTHREADS 512                  // 16 warps: 4x4 grid, warp tile 32x64
#define NSTAGE 3

// smem rows: 32 halves data + 8 pad = 80 B per row (conflict-free ldmatrix)
#define ROWB 80
#define ABUF_BYTES (128 * ROWB)       // 10240
#define BBUF_BYTES (256 * ROWB)       // 20480
#define OFF_BHI (2 * ABUF_BYTES)
#define STAGE_BYTES (2 * ABUF_BYTES + 2 * BBUF_BYTES)   // 61440
#define SMEM_GEMM (NSTAGE * STAGE_BYTES)                // 184320

// ---------------------------------------------------------------------------
// Scratch
// ---------------------------------------------------------------------------
__device__ __half g_Ahi[(size_t)MROWS * CDIM];
__device__ __half g_Alo[(size_t)MROWS * CDIM];
__device__ __half g_Bhi[(size_t)KCODES * CDIM];
__device__ __half g_Blo[(size_t)KCODES * CDIM];
__device__ float  g_rowsum[MROWS];

// ---------------------------------------------------------------------------
// PTX helpers
// ---------------------------------------------------------------------------
__device__ __forceinline__ uint32_t smem_u32(const void* p) {
    uint32_t a;
    asm("{ .reg .u64 t; cvta.to.shared.u64 t, %1; cvt.u32.u64 %0, t; }" : "=r"(a) : "l"(p));
    return a;
}
#define CP_ASYNC16(dst, src) \
    asm volatile("cp.async.cg.shared.global [%0], [%1], 16;\n" :: "r"(dst), "l"(src))
#define CP_COMMIT() asm volatile("cp.async.commit_group;\n" ::: "memory")
#define CP_WAIT2()  asm volatile("cp.async.wait_group 2;\n" ::: "memory")
#define CP_WAIT1()  asm volatile("cp.async.wait_group 1;\n" ::: "memory")
#define CP_WAIT0()  asm volatile("cp.async.wait_group 0;\n" ::: "memory")

__device__ __forceinline__ void ldsm_x4(uint32_t* r, uint32_t addr) {
    asm volatile("ldmatrix.sync.aligned.m8n8.x4.shared.b16 {%0,%1,%2,%3}, [%4];"
                 : "=r"(r[0]), "=r"(r[1]), "=r"(r[2]), "=r"(r[3]) : "r"(addr));
}
__device__ __forceinline__ void mma16816(float* c, const uint32_t* a, uint32_t b0, uint32_t b1) {
    asm volatile("mma.sync.aligned.m16n8k16.row.col.f32.f16.f16.f32 "
                 "{%0,%1,%2,%3}, {%4,%5,%6,%7}, {%8,%9}, {%0,%1,%2,%3};"
                 : "+f"(c[0]), "+f"(c[1]), "+f"(c[2]), "+f"(c[3])
                 : "r"(a[0]), "r"(a[1]), "r"(a[2]), "r"(a[3]), "r"(b0), "r"(b1));
}

// ---------------------------------------------------------------------------
// Kernel 1: row inv-L2-norm; write fp16 hi/lo of xn; zero rowsum.
// ---------------------------------------------------------------------------
__global__ void prep_x_kernel(const float* __restrict__ x) {
    int gw = (blockIdx.x * blockDim.x + threadIdx.x) >> 5;
    int lane = threadIdx.x & 31;
    if (gw >= MROWS) return;
    int n = gw / LTOK, l = gw % LTOK;
    const float4* r4 = (const float4*)(x + ((size_t)n * 197 + l + 1) * CDIM);

    float4 v[6];
    float s = 0.0f;
#pragma unroll
    for (int i = 0; i < 6; ++i) {
        v[i] = r4[lane + i * 32];
        s += v[i].x * v[i].x + v[i].y * v[i].y + v[i].z * v[i].z + v[i].w * v[i].w;
    }
#pragma unroll
    for (int o = 16; o > 0; o >>= 1) s += __shfl_xor_sync(0xffffffffu, s, o);
    float inv = 1.0f / fmaxf(sqrtf(s), NORM_EPS);

    uint2* ah = (uint2*)(g_Ahi + (size_t)gw * CDIM);
    uint2* al = (uint2*)(g_Alo + (size_t)gw * CDIM);
#pragma unroll
    for (int i = 0; i < 6; ++i) {
        float a[4] = {v[i].x * inv, v[i].y * inv, v[i].z * inv, v[i].w * inv};
        __half h[4], lo[4];
#pragma unroll
        for (int c = 0; c < 4; ++c) {
            h[c]  = __float2half_rn(a[c]);
            lo[c] = __float2half_rn(a[c] - __half2float(h[c]));
        }
        int idx = lane + i * 32;
        ah[idx] = *(uint2*)h;
        al[idx] = *(uint2*)lo;
    }
    if (lane == 0) g_rowsum[gw] = 0.0f;
}

// ---------------------------------------------------------------------------
// Kernel 2: embedding -> fp16 hi/lo.
// ---------------------------------------------------------------------------
__global__ void conv_emb_kernel(const float* __restrict__ emb) {
    size_t i = (size_t)blockIdx.x * blockDim.x + threadIdx.x;
    float4 e = ((const float4*)emb)[i];
    float a[4] = {e.x, e.y, e.z, e.w};
    __half h[4], lo[4];
#pragma unroll
    for (int c = 0; c < 4; ++c) {
        h[c]  = __float2half_rn(a[c]);
        lo[c] = __float2half_rn(a[c] - __half2float(h[c]));
    }
    ((uint2*)g_Bhi)[i] = *(uint2*)h;
    ((uint2*)g_Blo)[i] = *(uint2*)lo;
}

// No-op kernel: shifts the ncu fixed sampling slot so gemm gets profiled.
__global__ void noop_kernel() {}

// ---------------------------------------------------------------------------
// Kernel 3: HMMA GEMM (fp16 2-term split, 3 MMA products) + fused exp epilogue.
// CTA 128x256, 512 threads (16 warps, warp tile 32x64), 3-stage pipeline.
// acc = 64 floats/thread -> ~110 regs, no spills at the 128-reg/512t cap.
// ---------------------------------------------------------------------------
__device__ __forceinline__ void load_stage(uint32_t stage_sb, int k0, int row0, int col0, int tid) {
    // A: 2 bufs x 128 rows x 4 chunks = 1024 chunks; 2 per thread
#pragma unroll
    for (int j = 0; j < 2; ++j) {
        int c = tid * 2 + j;
        int buf = c >> 9;
        int rem = c & 511;
        int row = rem >> 2, ch = rem & 3;
        const __half* src = (buf ? g_Alo : g_Ahi) + (size_t)(row0 + row) * CDIM + k0 + ch * 8;
        CP_ASYNC16(stage_sb + buf * ABUF_BYTES + row * ROWB + ch * 16, src);
    }
    // B: 2 bufs x 256 rows x 4 chunks = 2048 chunks; 4 per thread
#pragma unroll
    for (int j = 0; j < 4; ++j) {
        int c = tid * 4 + j;
        int buf = c >> 10;
        int rem = c & 1023;
        int row = rem >> 2, ch = rem & 3;
        const __half* src = (buf ? g_Blo : g_Bhi) + (size_t)(col0 + row) * CDIM + k0 + ch * 8;
        CP_ASYNC16(stage_sb + OFF_BHI + buf * BBUF_BYTES + row * ROWB + ch * 16, src);
    }
    CP_COMMIT();
}

__global__ __launch_bounds__(GTHREADS, 1) void gemm_exp_kernel(float* __restrict__ codes) {
    extern __shared__ char smem[];
    const uint32_t sb = smem_u32(smem);
    const int tid  = threadIdx.x;
    const int lane = tid & 31;
    const int warp = tid >> 5;
    const int wm = warp >> 2;              // 0..3 (32-row stripes)
    const int wn = warp & 3;               // 0..3 (64-col stripes)
    const int row0 = blockIdx.y * BM;
    const int col0 = blockIdx.x * BN;

    const int lm = lane & 7;
    const int lg = lane >> 3;

    const int a_row = wm * 32 + lm + (lg & 1) * 8;      // + mf*16
    const int a_kk  = (lg >> 1) * 8;
    const int b_row = wn * 64 + lm + (lg >> 1) * 8;     // + nf2*16
    const int b_kk  = (lg & 1) * 8;

    float acc[2][8][4];
#pragma unroll
    for (int i = 0; i < 2; ++i)
#pragma unroll
        for (int j = 0; j < 8; ++j)
#pragma unroll
            for (int c = 0; c < 4; ++c) acc[i][j][c] = 0.0f;

    load_stage(sb + 0 * STAGE_BYTES, 0 * BK, row0, col0, tid);
    load_stage(sb + 1 * STAGE_BYTES, 1 * BK, row0, col0, tid);
    load_stage(sb + 2 * STAGE_BYTES, 2 * BK, row0, col0, tid);

    for (int i = 0; i < NCHUNK; ++i) {
        if (i < NCHUNK - 2)      { CP_WAIT2(); }
        else if (i == NCHUNK - 2){ CP_WAIT1(); }
        else                     { CP_WAIT0(); }
        __syncthreads();

        const uint32_t sA = sb + (i % NSTAGE) * STAGE_BYTES;
        const uint32_t sB = sA + OFF_BHI;

#pragma unroll
        for (int ks = 0; ks < 2; ++ks) {
            uint32_t aH[2][4], aL[2][4];
#pragma unroll
            for (int mf = 0; mf < 2; ++mf) {
                uint32_t aoff = (uint32_t)((a_row + mf * 16) * ROWB + (ks * 16 + a_kk) * 2);
                ldsm_x4(aH[mf], sA + aoff);
                ldsm_x4(aL[mf], sA + ABUF_BYTES + aoff);
            }
#pragma unroll
            for (int nf2 = 0; nf2 < 4; ++nf2) {
                uint32_t bH[4], bL[4];
                uint32_t boff = (uint32_t)((b_row + nf2 * 16) * ROWB + (ks * 16 + b_kk) * 2);
                ldsm_x4(bH, sB + boff);
                ldsm_x4(bL, sB + BBUF_BYTES + boff);
#pragma unroll
                for (int mf = 0; mf < 2; ++mf) {
                    mma16816(acc[mf][nf2 * 2 + 0], aH[mf], bH[0], bH[1]);
                    mma16816(acc[mf][nf2 * 2 + 1], aH[mf], bH[2], bH[3]);
                    mma16816(acc[mf][nf2 * 2 + 0], aH[mf], bL[0], bL[1]);
                    mma16816(acc[mf][nf2 * 2 + 1], aH[mf], bL[2], bL[3]);
                    mma16816(acc[mf][nf2 * 2 + 0], aL[mf], bH[0], bH[1]);
                    mma16816(acc[mf][nf2 * 2 + 1], aL[mf], bH[2], bH[3]);
                }
            }
        }

        __syncthreads();
        if (i + NSTAGE < NCHUNK)
            load_stage(sb + (i % NSTAGE) * STAGE_BYTES, (i + NSTAGE) * BK, row0, col0, tid);
    }

    // Epilogue: p = exp(30*d - 30); coalesced v2 stores; rowsum atomics.
#pragma unroll
    for (int mf = 0; mf < 2; ++mf) {
        int gr = row0 + wm * 32 + mf * 16 + (lane >> 2);   // rows gr and gr+8
        float s0 = 0.0f, s1 = 0.0f;
#pragma unroll
        for (int nf = 0; nf < 8; ++nf) {
            float* c = acc[mf][nf];
            float2 p0, p1;
            p0.x = __expf(fmaf(INV_DELTA_EFF, c[0], -INV_DELTA_EFF));
            p0.y = __expf(fmaf(INV_DELTA_EFF, c[1], -INV_DELTA_EFF));
            p1.x = __expf(fmaf(INV_DELTA_EFF, c[2], -INV_DELTA_EFF));
            p1.y = __expf(fmaf(INV_DELTA_EFF, c[3], -INV_DELTA_EFF));
            int gc = col0 + wn * 64 + nf * 8 + (lane & 3) * 2;
            *(float2*)(codes + (size_t)gr * KCODES + gc)       = p0;
            *(float2*)(codes + (size_t)(gr + 8) * KCODES + gc) = p1;
            s0 += p0.x + p0.y;
            s1 += p1.x + p1.y;
        }
        s0 += __shfl_xor_sync(0xffffffffu, s0, 1);
        s0 += __shfl_xor_sync(0xffffffffu, s0, 2);
        s1 += __shfl_xor_sync(0xffffffffu, s1, 1);
        s1 += __shfl_xor_sync(0xffffffffu, s1, 2);
        if ((lane & 3) == 0) {
            atomicAdd(&g_rowsum[gr], s0);
            atomicAdd(&g_rowsum[gr + 8], s1);
        }
    }
}

// ---------------------------------------------------------------------------
// Kernel 4: softmax normalize codes (float4 elementwise)
// ---------------------------------------------------------------------------
__global__ void scale_kernel(float* __restrict__ codes) {
    size_t i = (size_t)blockIdx.x * blockDim.x + threadIdx.x;
    size_t r = i >> 10;
    float inv = 1.0f / g_rowsum[r];
    float4 v = ((float4*)codes)[i];
    v.x *= inv; v.y *= inv; v.z *= inv; v.w *= inv;
    ((float4*)codes)[i] = v;
}

// ---------------------------------------------------------------------------
// Kernel 5a: bow partial means. grid (128, 16), 64 threads.
// ---------------------------------------------------------------------------
__global__ __launch_bounds__(64) void bow_partial_kernel(
    const float* __restrict__ codes, float* __restrict__ bow)
{
    int n = blockIdx.x, kc = blockIdx.y, t = threadIdx.x;
    int col = kc * 256 + t * 4;
    float4 acc = make_float4(0.f, 0.f, 0.f, 0.f);
#pragma unroll 1
    for (int rr = 2; rr < 12; ++rr) {
#pragma unroll
        for (int cc = 2; cc < 12; ++cc) {
            int l = rr * 14 + cc;
            float4 v = *(const float4*)(codes + ((size_t)n * LTOK + l) * KCODES + col);
            acc.x += v.x; acc.y += v.y; acc.z += v.z; acc.w += v.w;
        }
    }
    acc.x *= 0.01f; acc.y *= 0.01f; acc.z *= 0.01f; acc.w *= 0.01f;
    *(float4*)(bow + (size_t)n * KCODES + col) = acc;
}

// ---------------------------------------------------------------------------
// Kernel 5b: L1-normalize bow rows.
// ---------------------------------------------------------------------------
__global__ __launch_bounds__(256) void bow_norm_kernel(float* __restrict__ bow) {
    int n = blockIdx.x, t = threadIdx.x;
    float4* row = (float4*)(bow + (size_t)n * KCODES);
    float4 v[4];
    float s = 0.0f;
#pragma unroll
    for (int j = 0; j < 4; ++j) {
        v[j] = row[t + j * 256];
        s += fabsf(v[j].x) + fabsf(v[j].y) + fabsf(v[j].z) + fabsf(v[j].w);
    }
    __shared__ float sred[256];
    sred[t] = s;
    __syncthreads();
    for (int o = 128; o > 0; o >>= 1) {
        if (t < o) sred[t] += sred[t + o];
        __syncthreads();
    }
    float inv = 1.0f / fmaxf(sred[0], NORM_EPS);
#pragma unroll
    for (int j = 0; j < 4; ++j) {
        v[j].x *= inv; v[j].y *= inv; v[j].z *= inv; v[j].w *= inv;
        row[t + j * 256] = v[j];
    }
}

// ---------------------------------------------------------------------------
// Launch
// ---------------------------------------------------------------------------
extern "C" void kernel_launch(void* const* d_in, const int* in_sizes, int n_in,
                              void* d_out, int out_size) {
    const float* x   = (const float*)d_in[0];
    const float* emb = (const float*)d_in[1];
    float* out_bow   = (float*)d_out;
    float* out_codes = (float*)d_out + (size_t)NBATCH * KCODES;

    cudaFuncSetAttribute(gemm_exp_kernel, cudaFuncAttributeMaxDynamicSharedMemorySize,
                         SMEM_GEMM);

    prep_x_kernel<<<MROWS * 32 / 256, 256>>>(x);
    conv_emb_kernel<<<(KCODES * CDIM / 4) / 256, 256>>>(emb);

    noop_kernel<<<1, 32>>>();   // shift ncu fixed sampling slot onto the GEMM

    gemm_exp_kernel<<<dim3(KCODES / BN, MROWS / BM), GTHREADS, SMEM_GEMM>>>(out_codes);

    {
        size_t nf4 = (size_t)MROWS * KCODES / 4;
        scale_kernel<<<(int)(nf4 / 256), 256>>>(out_codes);
    }
    bow_partial_kernel<<<dim3(NBATCH, 16), 64>>>(out_codes, out_bow);
    bow_norm_kernel<<<NBATCH, 256>>>(out_bow);
}

// round 8
// speedup vs baseline: 3.4802x; 1.2784x over previous
#include <cuda_runtime.h>
#include <cuda_fp16.h>
#include <cstdint>
#include <math.h>

// ---------------------------------------------------------------------------
// Problem constants
// ---------------------------------------------------------------------------
#define NBATCH 128
#define LTOK   196
#define CDIM   768
#define KCODES 4096
#define MROWS  (NBATCH * LTOK)        // 25088
#define INV_DELTA_EFF 30.0f           // 15.0 / 0.5
#define NORM_EPS 1e-5f

// GEMM tiling (portable HMMA mma.sync path)
#define BM 128
#define BN 256
#define BK 32
#define NCHUNK (CDIM / BK)            // 24
#define GTHREADS 512                  // 16 warps: 4x4 grid, warp tile 32x64
#define NSTAGE 4

// smem rows: 32 halves data + 8 pad = 80 B per row (conflict-free ldmatrix)
#define ROWB 80
#define ABUF_BYTES (128 * ROWB)       // 10240  (A hi only)
#define BBUF_BYTES (256 * ROWB)       // 20480
#define OFF_BHI ABUF_BYTES
#define OFF_BLO (ABUF_BYTES + BBUF_BYTES)
#define STAGE_BYTES (ABUF_BYTES + 2 * BBUF_BYTES)       // 51200
#define SMEM_GEMM (NSTAGE * STAGE_BYTES)                // 204800

// ---------------------------------------------------------------------------
// Scratch
// ---------------------------------------------------------------------------
__device__ __half g_Ahi[(size_t)MROWS * CDIM];
__device__ __half g_Bhi[(size_t)KCODES * CDIM];
__device__ __half g_Blo[(size_t)KCODES * CDIM];
__device__ float  g_rowsum[MROWS];

// ---------------------------------------------------------------------------
// PTX helpers
// ---------------------------------------------------------------------------
__device__ __forceinline__ uint32_t smem_u32(const void* p) {
    uint32_t a;
    asm("{ .reg .u64 t; cvta.to.shared.u64 t, %1; cvt.u32.u64 %0, t; }" : "=r"(a) : "l"(p));
    return a;
}
#define CP_ASYNC16(dst, src) \
    asm volatile("cp.async.cg.shared.global [%0], [%1], 16;\n" :: "r"(dst), "l"(src))
#define CP_COMMIT() asm volatile("cp.async.commit_group;\n" ::: "memory")
#define CP_WAIT2()  asm volatile("cp.async.wait_group 2;\n" ::: "memory")
#define CP_WAIT1()  asm volatile("cp.async.wait_group 1;\n" ::: "memory")
#define CP_WAIT0()  asm volatile("cp.async.wait_group 0;\n" ::: "memory")

__device__ __forceinline__ void ldsm_x4(uint32_t* r, uint32_t addr) {
    asm volatile("ldmatrix.sync.aligned.m8n8.x4.shared.b16 {%0,%1,%2,%3}, [%4];"
                 : "=r"(r[0]), "=r"(r[1]), "=r"(r[2]), "=r"(r[3]) : "r"(addr));
}
__device__ __forceinline__ void mma16816(float* c, const uint32_t* a, uint32_t b0, uint32_t b1) {
    asm volatile("mma.sync.aligned.m16n8k16.row.col.f32.f16.f16.f32 "
                 "{%0,%1,%2,%3}, {%4,%5,%6,%7}, {%8,%9}, {%0,%1,%2,%3};"
                 : "+f"(c[0]), "+f"(c[1]), "+f"(c[2]), "+f"(c[3])
                 : "r"(a[0]), "r"(a[1]), "r"(a[2]), "r"(a[3]), "r"(b0), "r"(b1));
}

// ---------------------------------------------------------------------------
// Kernel 1: row inv-L2-norm; write fp16 hi of xn; zero rowsum.
// ---------------------------------------------------------------------------
__global__ void prep_x_kernel(const float* __restrict__ x) {
    int gw = (blockIdx.x * blockDim.x + threadIdx.x) >> 5;
    int lane = threadIdx.x & 31;
    if (gw >= MROWS) return;
    int n = gw / LTOK, l = gw % LTOK;
    const float4* r4 = (const float4*)(x + ((size_t)n * 197 + l + 1) * CDIM);

    float4 v[6];
    float s = 0.0f;
#pragma unroll
    for (int i = 0; i < 6; ++i) {
        v[i] = r4[lane + i * 32];
        s += v[i].x * v[i].x + v[i].y * v[i].y + v[i].z * v[i].z + v[i].w * v[i].w;
    }
#pragma unroll
    for (int o = 16; o > 0; o >>= 1) s += __shfl_xor_sync(0xffffffffu, s, o);
    float inv = 1.0f / fmaxf(sqrtf(s), NORM_EPS);

    uint2* ah = (uint2*)(g_Ahi + (size_t)gw * CDIM);
#pragma unroll
    for (int i = 0; i < 6; ++i) {
        float a[4] = {v[i].x * inv, v[i].y * inv, v[i].z * inv, v[i].w * inv};
        __half h[4];
#pragma unroll
        for (int c = 0; c < 4; ++c) h[c] = __float2half_rn(a[c]);
        ah[lane + i * 32] = *(uint2*)h;
    }
    if (lane == 0) g_rowsum[gw] = 0.0f;
}

// ---------------------------------------------------------------------------
// Kernel 2: embedding -> fp16 hi/lo (B stays exactly represented as hi+lo).
// ---------------------------------------------------------------------------
__global__ void conv_emb_kernel(const float* __restrict__ emb) {
    size_t i = (size_t)blockIdx.x * blockDim.x + threadIdx.x;
    float4 e = ((const float4*)emb)[i];
    float a[4] = {e.x, e.y, e.z, e.w};
    __half h[4], lo[4];
#pragma unroll
    for (int c = 0; c < 4; ++c) {
        h[c]  = __float2half_rn(a[c]);
        lo[c] = __float2half_rn(a[c] - __half2float(h[c]));
    }
    ((uint2*)g_Bhi)[i] = *(uint2*)h;
    ((uint2*)g_Blo)[i] = *(uint2*)lo;
}

// No-op kernel: keeps ncu's fixed sampling slot on the GEMM.
__global__ void noop_kernel() {}

// ---------------------------------------------------------------------------
// Kernel 3: HMMA GEMM  d = ah·(bh+bl)  + fused exp epilogue.
// CTA 128x256, 512 threads (16 warps, warp tile 32x64),
// 4-stage single-barrier cp.async pipeline.
// ---------------------------------------------------------------------------
__device__ __forceinline__ void load_stage(uint32_t stage_sb, int k0, int row0, int col0, int tid) {
    // A hi: 128 rows x 4 chunks = 512 chunks; 1 per thread
    {
        int row = tid >> 2, ch = tid & 3;
        const __half* src = g_Ahi + (size_t)(row0 + row) * CDIM + k0 + ch * 8;
        CP_ASYNC16(stage_sb + row * ROWB + ch * 16, src);
    }
    // B hi/lo: 2 bufs x 256 rows x 4 chunks = 2048 chunks; 4 per thread
#pragma unroll
    for (int j = 0; j < 4; ++j) {
        int c = tid * 4 + j;
        int buf = c >> 10;
        int rem = c & 1023;
        int row = rem >> 2, ch = rem & 3;
        const __half* src = (buf ? g_Blo : g_Bhi) + (size_t)(col0 + row) * CDIM + k0 + ch * 8;
        CP_ASYNC16(stage_sb + OFF_BHI + buf * BBUF_BYTES + row * ROWB + ch * 16, src);
    }
    CP_COMMIT();
}

__global__ __launch_bounds__(GTHREADS, 1) void gemm_exp_kernel(float* __restrict__ codes) {
    extern __shared__ char smem[];
    const uint32_t sb = smem_u32(smem);
    const int tid  = threadIdx.x;
    const int lane = tid & 31;
    const int warp = tid >> 5;
    const int wm = warp >> 2;              // 0..3 (32-row stripes)
    const int wn = warp & 3;               // 0..3 (64-col stripes)
    const int row0 = blockIdx.y * BM;
    const int col0 = blockIdx.x * BN;

    const int lm = lane & 7;
    const int lg = lane >> 3;

    const int a_row = wm * 32 + lm + (lg & 1) * 8;      // + mf*16
    const int a_kk  = (lg >> 1) * 8;
    const int b_row = wn * 64 + lm + (lg >> 1) * 8;     // + nf2*16
    const int b_kk  = (lg & 1) * 8;

    float acc[2][8][4];
#pragma unroll
    for (int i = 0; i < 2; ++i)
#pragma unroll
        for (int j = 0; j < 8; ++j)
#pragma unroll
            for (int c = 0; c < 4; ++c) acc[i][j][c] = 0.0f;

    load_stage(sb + 0 * STAGE_BYTES, 0 * BK, row0, col0, tid);
    load_stage(sb + 1 * STAGE_BYTES, 1 * BK, row0, col0, tid);
    load_stage(sb + 2 * STAGE_BYTES, 2 * BK, row0, col0, tid);

    for (int i = 0; i < NCHUNK; ++i) {
        if (i < NCHUNK - 2)      { CP_WAIT2(); }
        else if (i == NCHUNK - 2){ CP_WAIT1(); }
        else                     { CP_WAIT0(); }
        __syncthreads();

        // Prefetch stage i+3 into the slot consumed in iteration i-1 (safe:
        // the barrier above guarantees all warps finished reading it).
        if (i + 3 < NCHUNK)
            load_stage(sb + ((i + 3) % NSTAGE) * STAGE_BYTES, (i + 3) * BK, row0, col0, tid);

        const uint32_t sA = sb + (i % NSTAGE) * STAGE_BYTES;
        const uint32_t sB = sA + OFF_BHI;

#pragma unroll
        for (int ks = 0; ks < 2; ++ks) {
            uint32_t aH[2][4];
#pragma unroll
            for (int mf = 0; mf < 2; ++mf) {
                uint32_t aoff = (uint32_t)((a_row + mf * 16) * ROWB + (ks * 16 + a_kk) * 2);
                ldsm_x4(aH[mf], sA + aoff);
            }
#pragma unroll
            for (int nf2 = 0; nf2 < 4; ++nf2) {
                uint32_t bH[4], bL[4];
                uint32_t boff = (uint32_t)((b_row + nf2 * 16) * ROWB + (ks * 16 + b_kk) * 2);
                ldsm_x4(bH, sB + boff);
                ldsm_x4(bL, sB + BBUF_BYTES + boff);
#pragma unroll
                for (int mf = 0; mf < 2; ++mf) {
                    mma16816(acc[mf][nf2 * 2 + 0], aH[mf], bH[0], bH[1]);
                    mma16816(acc[mf][nf2 * 2 + 1], aH[mf], bH[2], bH[3]);
                    mma16816(acc[mf][nf2 * 2 + 0], aH[mf], bL[0], bL[1]);
                    mma16816(acc[mf][nf2 * 2 + 1], aH[mf], bL[2], bL[3]);
                }
            }
        }
    }

    // Epilogue: p = exp(30*d - 30); coalesced v2 stores; rowsum atomics.
#pragma unroll
    for (int mf = 0; mf < 2; ++mf) {
        int gr = row0 + wm * 32 + mf * 16 + (lane >> 2);   // rows gr and gr+8
        float s0 = 0.0f, s1 = 0.0f;
#pragma unroll
        for (int nf = 0; nf < 8; ++nf) {
            float* c = acc[mf][nf];
            float2 p0, p1;
            p0.x = __expf(fmaf(INV_DELTA_EFF, c[0], -INV_DELTA_EFF));
            p0.y = __expf(fmaf(INV_DELTA_EFF, c[1], -INV_DELTA_EFF));
            p1.x = __expf(fmaf(INV_DELTA_EFF, c[2], -INV_DELTA_EFF));
            p1.y = __expf(fmaf(INV_DELTA_EFF, c[3], -INV_DELTA_EFF));
            int gc = col0 + wn * 64 + nf * 8 + (lane & 3) * 2;
            *(float2*)(codes + (size_t)gr * KCODES + gc)       = p0;
            *(float2*)(codes + (size_t)(gr + 8) * KCODES + gc) = p1;
            s0 += p0.x + p0.y;
            s1 += p1.x + p1.y;
        }
        s0 += __shfl_xor_sync(0xffffffffu, s0, 1);
        s0 += __shfl_xor_sync(0xffffffffu, s0, 2);
        s1 += __shfl_xor_sync(0xffffffffu, s1, 1);
        s1 += __shfl_xor_sync(0xffffffffu, s1, 2);
        if ((lane & 3) == 0) {
            atomicAdd(&g_rowsum[gr], s0);
            atomicAdd(&g_rowsum[gr + 8], s1);
        }
    }
}

// ---------------------------------------------------------------------------
// Kernel 4: softmax normalize codes (float4 elementwise)
// ---------------------------------------------------------------------------
__global__ void scale_kernel(float* __restrict__ codes) {
    size_t i = (size_t)blockIdx.x * blockDim.x + threadIdx.x;
    size_t r = i >> 10;
    float inv = 1.0f / g_rowsum[r];
    float4 v = ((float4*)codes)[i];
    v.x *= inv; v.y *= inv; v.z *= inv; v.w *= inv;
    ((float4*)codes)[i] = v;
}

// ---------------------------------------------------------------------------
// Kernel 5a: bow partial means. grid (128, 16), 64 threads.
// ---------------------------------------------------------------------------
__global__ __launch_bounds__(64) void bow_partial_kernel(
    const float* __restrict__ codes, float* __restrict__ bow)
{
    int n = blockIdx.x, kc = blockIdx.y, t = threadIdx.x;
    int col = kc * 256 + t * 4;
    float4 acc = make_float4(0.f, 0.f, 0.f, 0.f);
#pragma unroll 1
    for (int rr = 2; rr < 12; ++rr) {
#pragma unroll
        for (int cc = 2; cc < 12; ++cc) {
            int l = rr * 14 + cc;
            float4 v = *(const float4*)(codes + ((size_t)n * LTOK + l) * KCODES + col);
            acc.x += v.x; acc.y += v.y; acc.z += v.z; acc.w += v.w;
        }
    }
    acc.x *= 0.01f; acc.y *= 0.01f; acc.z *= 0.01f; acc.w *= 0.01f;
    *(float4*)(bow + (size_t)n * KCODES + col) = acc;
}

// ---------------------------------------------------------------------------
// Kernel 5b: L1-normalize bow rows.
// ---------------------------------------------------------------------------
__global__ __launch_bounds__(256) void bow_norm_kernel(float* __restrict__ bow) {
    int n = blockIdx.x, t = threadIdx.x;
    float4* row = (float4*)(bow + (size_t)n * KCODES);
    float4 v[4];
    float s = 0.0f;
#pragma unroll
    for (int j = 0; j < 4; ++j) {
        v[j] = row[t + j * 256];
        s += fabsf(v[j].x) + fabsf(v[j].y) + fabsf(v[j].z) + fabsf(v[j].w);
    }
    __shared__ float sred[256];
    sred[t] = s;
    __syncthreads();
    for (int o = 128; o > 0; o >>= 1) {
        if (t < o) sred[t] += sred[t + o];
        __syncthreads();
    }
    float inv = 1.0f / fmaxf(sred[0], NORM_EPS);
#pragma unroll
    for (int j = 0; j < 4; ++j) {
        v[j].x *= inv; v[j].y *= inv; v[j].z *= inv; v[j].w *= inv;
        row[t + j * 256] = v[j];
    }
}

// ---------------------------------------------------------------------------
// Launch
// ---------------------------------------------------------------------------
extern "C" void kernel_launch(void* const* d_in, const int* in_sizes, int n_in,
                              void* d_out, int out_size) {
    const float* x   = (const float*)d_in[0];
    const float* emb = (const float*)d_in[1];
    float* out_bow   = (float*)d_out;
    float* out_codes = (float*)d_out + (size_t)NBATCH * KCODES;

    cudaFuncSetAttribute(gemm_exp_kernel, cudaFuncAttributeMaxDynamicSharedMemorySize,
                         SMEM_GEMM);

    prep_x_kernel<<<MROWS * 32 / 256, 256>>>(x);
    conv_emb_kernel<<<(KCODES * CDIM / 4) / 256, 256>>>(emb);

    noop_kernel<<<1, 32>>>();   // keep ncu fixed sampling slot on the GEMM

    gemm_exp_kernel<<<dim3(KCODES / BN, MROWS / BM), GTHREADS, SMEM_GEMM>>>(out_codes);

    {
        size_t nf4 = (size_t)MROWS * KCODES / 4;
        scale_kernel<<<(int)(nf4 / 256), 256>>>(out_codes);
    }
    bow_partial_kernel<<<dim3(NBATCH, 16), 64>>>(out_codes, out_bow);
    bow_norm_kernel<<<NBATCH, 256>>>(out_bow);
}

// round 10
// speedup vs baseline: 4.5543x; 1.3086x over previous
#include <cuda_runtime.h>
#include <cuda_fp16.h>
#include <cstdint>
#include <math.h>

// ---------------------------------------------------------------------------
// Problem constants
// ---------------------------------------------------------------------------
#define NBATCH 128
#define LTOK   196
#define CDIM   768
#define KCODES 4096
#define MROWS  (NBATCH * LTOK)        // 25088
#define INV_DELTA_EFF 30.0f           // 15.0 / 0.5
#define NORM_EPS 1e-5f

// GEMM tiling (portable HMMA mma.sync path)
#define BM 128
#define BN 256
#define BK 32
#define NCHUNK (CDIM / BK)            // 24
#define GTHREADS 512                  // 16 warps: 4x4 grid, warp tile 32x64
#define NSTAGE 5

// smem rows: 32 halves data + 8 pad = 80 B per row (conflict-free ldmatrix)
#define ROWB 80
#define ABUF_BYTES (128 * ROWB)       // 10240 (per A buf: hi, lo)
#define BBUF_BYTES (256 * ROWB)       // 20480 (B hi only)
#define OFF_ALO ABUF_BYTES
#define OFF_BHI (2 * ABUF_BYTES)
#define STAGE_BYTES (2 * ABUF_BYTES + BBUF_BYTES)       // 40960
#define SMEM_GEMM (NSTAGE * STAGE_BYTES)                // 204800

// ---------------------------------------------------------------------------
// Scratch
// ---------------------------------------------------------------------------
__device__ __half g_Ahi[(size_t)MROWS * CDIM];
__device__ __half g_Alo[(size_t)MROWS * CDIM];
__device__ __half g_Bhi[(size_t)KCODES * CDIM];
__device__ float  g_rowsum[MROWS];

// ---------------------------------------------------------------------------
// PTX helpers
// ---------------------------------------------------------------------------
__device__ __forceinline__ uint32_t smem_u32(const void* p) {
    uint32_t a;
    asm("{ .reg .u64 t; cvta.to.shared.u64 t, %1; cvt.u32.u64 %0, t; }" : "=r"(a) : "l"(p));
    return a;
}
#define CP_ASYNC16(dst, src) \
    asm volatile("cp.async.cg.shared.global [%0], [%1], 16;\n" :: "r"(dst), "l"(src))
#define CP_COMMIT() asm volatile("cp.async.commit_group;\n" ::: "memory")
#define CP_WAIT3()  asm volatile("cp.async.wait_group 3;\n" ::: "memory")
#define CP_WAIT2()  asm volatile("cp.async.wait_group 2;\n" ::: "memory")
#define CP_WAIT1()  asm volatile("cp.async.wait_group 1;\n" ::: "memory")
#define CP_WAIT0()  asm volatile("cp.async.wait_group 0;\n" ::: "memory")

__device__ __forceinline__ void ldsm_x4(uint32_t* r, uint32_t addr) {
    asm volatile("ldmatrix.sync.aligned.m8n8.x4.shared.b16 {%0,%1,%2,%3}, [%4];"
                 : "=r"(r[0]), "=r"(r[1]), "=r"(r[2]), "=r"(r[3]) : "r"(addr));
}
__device__ __forceinline__ void mma16816(float* c, const uint32_t* a, uint32_t b0, uint32_t b1) {
    asm volatile("mma.sync.aligned.m16n8k16.row.col.f32.f16.f16.f32 "
                 "{%0,%1,%2,%3}, {%4,%5,%6,%7}, {%8,%9}, {%0,%1,%2,%3};"
                 : "+f"(c[0]), "+f"(c[1]), "+f"(c[2]), "+f"(c[3])
                 : "r"(a[0]), "r"(a[1]), "r"(a[2]), "r"(a[3]), "r"(b0), "r"(b1));
}

// ---------------------------------------------------------------------------
// Kernel 1: row inv-L2-norm; write fp16 hi/lo of xn; zero rowsum.
// ---------------------------------------------------------------------------
__global__ void prep_x_kernel(const float* __restrict__ x) {
    int gw = (blockIdx.x * blockDim.x + threadIdx.x) >> 5;
    int lane = threadIdx.x & 31;
    if (gw >= MROWS) return;
    int n = gw / LTOK, l = gw % LTOK;
    const float4* r4 = (const float4*)(x + ((size_t)n * 197 + l + 1) * CDIM);

    float4 v[6];
    float s = 0.0f;
#pragma unroll
    for (int i = 0; i < 6; ++i) {
        v[i] = r4[lane + i * 32];
        s += v[i].x * v[i].x + v[i].y * v[i].y + v[i].z * v[i].z + v[i].w * v[i].w;
    }
#pragma unroll
    for (int o = 16; o > 0; o >>= 1) s += __shfl_xor_sync(0xffffffffu, s, o);
    float inv = 1.0f / fmaxf(sqrtf(s), NORM_EPS);

    uint2* ah = (uint2*)(g_Ahi + (size_t)gw * CDIM);
    uint2* al = (uint2*)(g_Alo + (size_t)gw * CDIM);
#pragma unroll
    for (int i = 0; i < 6; ++i) {
        float a[4] = {v[i].x * inv, v[i].y * inv, v[i].z * inv, v[i].w * inv};
        __half h[4], lo[4];
#pragma unroll
        for (int c = 0; c < 4; ++c) {
            h[c]  = __float2half_rn(a[c]);
            lo[c] = __float2half_rn(a[c] - __half2float(h[c]));
        }
        int idx = lane + i * 32;
        ah[idx] = *(uint2*)h;
        al[idx] = *(uint2*)lo;
    }
    if (lane == 0) g_rowsum[gw] = 0.0f;
}

// ---------------------------------------------------------------------------
// Kernel 2: embedding -> fp16 hi only (the a·b_lo term is dropped; ~2e-4).
// ---------------------------------------------------------------------------
__global__ void conv_emb_kernel(const float* __restrict__ emb) {
    size_t i = (size_t)blockIdx.x * blockDim.x + threadIdx.x;
    float4 e = ((const float4*)emb)[i];
    __half h[4];
    h[0] = __float2half_rn(e.x);
    h[1] = __float2half_rn(e.y);
    h[2] = __float2half_rn(e.z);
    h[3] = __float2half_rn(e.w);
    ((uint2*)g_Bhi)[i] = *(uint2*)h;
}

// No-op kernel: keeps ncu's fixed sampling slot on the GEMM.
__global__ void noop_kernel() {}

// ---------------------------------------------------------------------------
// Kernel 3: HMMA GEMM  d = (ah+al)·bh  + fused exp epilogue.
// CTA 128x256, 512 threads (16 warps, warp tile 32x64),
// 5-stage single-barrier cp.async pipeline. 8 ldsm per 16 HMMA (crossbar-
// balanced against the tensor pipe).
// ---------------------------------------------------------------------------
__device__ __forceinline__ void load_stage(uint32_t stage_sb, int k0, int row0, int col0, int tid) {
    // A hi + A lo: each 128 rows x 4 chunks = 512 chunks; 1 per thread each
    {
        int row = tid >> 2, ch = tid & 3;
        const __half* sh = g_Ahi + (size_t)(row0 + row) * CDIM + k0 + ch * 8;
        const __half* sl = g_Alo + (size_t)(row0 + row) * CDIM + k0 + ch * 8;
        uint32_t d = stage_sb + row * ROWB + ch * 16;
        CP_ASYNC16(d, sh);
        CP_ASYNC16(d + OFF_ALO, sl);
    }
    // B hi: 256 rows x 4 chunks = 1024 chunks; 2 per thread
#pragma unroll
    for (int j = 0; j < 2; ++j) {
        int c = tid * 2 + j;
        int row = c >> 2, ch = c & 3;
        const __half* src = g_Bhi + (size_t)(col0 + row) * CDIM + k0 + ch * 8;
        CP_ASYNC16(stage_sb + OFF_BHI + row * ROWB + ch * 16, src);
    }
    CP_COMMIT();
}

__global__ __launch_bounds__(GTHREADS, 1) void gemm_exp_kernel(float* __restrict__ codes) {
    extern __shared__ char smem[];
    const uint32_t sb = smem_u32(smem);
    const int tid  = threadIdx.x;
    const int lane = tid & 31;
    const int warp = tid >> 5;
    const int wm = warp >> 2;              // 0..3 (32-row stripes)
    const int wn = warp & 3;               // 0..3 (64-col stripes)
    const int row0 = blockIdx.y * BM;
    const int col0 = blockIdx.x * BN;

    const int lm = lane & 7;
    const int lg = lane >> 3;

    const int a_row = wm * 32 + lm + (lg & 1) * 8;      // + mf*16
    const int a_kk  = (lg >> 1) * 8;
    const int b_row = wn * 64 + lm + (lg >> 1) * 8;     // + nf2*16
    const int b_kk  = (lg & 1) * 8;

    float acc[2][8][4];
#pragma unroll
    for (int i = 0; i < 2; ++i)
#pragma unroll
        for (int j = 0; j < 8; ++j)
#pragma unroll
            for (int c = 0; c < 4; ++c) acc[i][j][c] = 0.0f;

    load_stage(sb + 0 * STAGE_BYTES, 0 * BK, row0, col0, tid);
    load_stage(sb + 1 * STAGE_BYTES, 1 * BK, row0, col0, tid);
    load_stage(sb + 2 * STAGE_BYTES, 2 * BK, row0, col0, tid);
    load_stage(sb + 3 * STAGE_BYTES, 3 * BK, row0, col0, tid);

    for (int i = 0; i < NCHUNK; ++i) {
        if (i < NCHUNK - 3)      { CP_WAIT3(); }
        else if (i == NCHUNK - 3){ CP_WAIT2(); }
        else if (i == NCHUNK - 2){ CP_WAIT1(); }
        else                     { CP_WAIT0(); }
        __syncthreads();

        // Prefetch stage i+4 into the slot consumed in iteration i-1 (safe:
        // the barrier above guarantees all warps finished reading it).
        if (i + 4 < NCHUNK)
            load_stage(sb + ((i + 4) % NSTAGE) * STAGE_BYTES, (i + 4) * BK, row0, col0, tid);

        const uint32_t sA = sb + (i % NSTAGE) * STAGE_BYTES;
        const uint32_t sB = sA + OFF_BHI;

#pragma unroll
        for (int ks = 0; ks < 2; ++ks) {
            uint32_t aH[2][4], aL[2][4];
#pragma unroll
            for (int mf = 0; mf < 2; ++mf) {
                uint32_t aoff = (uint32_t)((a_row + mf * 16) * ROWB + (ks * 16 + a_kk) * 2);
                ldsm_x4(aH[mf], sA + aoff);
                ldsm_x4(aL[mf], sA + OFF_ALO - OFF_BHI + (sB - sA) + aoff);  // = sA + OFF_ALO + aoff
            }
#pragma unroll
            for (int nf2 = 0; nf2 < 4; ++nf2) {
                uint32_t bH[4];
                uint32_t boff = (uint32_t)((b_row + nf2 * 16) * ROWB + (ks * 16 + b_kk) * 2);
                ldsm_x4(bH, sB + boff);
#pragma unroll
                for (int mf = 0; mf < 2; ++mf) {
                    mma16816(acc[mf][nf2 * 2 + 0], aH[mf], bH[0], bH[1]);
                    mma16816(acc[mf][nf2 * 2 + 1], aH[mf], bH[2], bH[3]);
                    mma16816(acc[mf][nf2 * 2 + 0], aL[mf], bH[0], bH[1]);
                    mma16816(acc[mf][nf2 * 2 + 1], aL[mf], bH[2], bH[3]);
                }
            }
        }
    }

    // Epilogue: p = exp(30*d - 30); coalesced v2 stores; rowsum atomics.
#pragma unroll
    for (int mf = 0; mf < 2; ++mf) {
        int gr = row0 + wm * 32 + mf * 16 + (lane >> 2);   // rows gr and gr+8
        float s0 = 0.0f, s1 = 0.0f;
#pragma unroll
        for (int nf = 0; nf < 8; ++nf) {
            float* c = acc[mf][nf];
            float2 p0, p1;
            p0.x = __expf(fmaf(INV_DELTA_EFF, c[0], -INV_DELTA_EFF));
            p0.y = __expf(fmaf(INV_DELTA_EFF, c[1], -INV_DELTA_EFF));
            p1.x = __expf(fmaf(INV_DELTA_EFF, c[2], -INV_DELTA_EFF));
            p1.y = __expf(fmaf(INV_DELTA_EFF, c[3], -INV_DELTA_EFF));
            int gc = col0 + wn * 64 + nf * 8 + (lane & 3) * 2;
            *(float2*)(codes + (size_t)gr * KCODES + gc)       = p0;
            *(float2*)(codes + (size_t)(gr + 8) * KCODES + gc) = p1;
            s0 += p0.x + p0.y;
            s1 += p1.x + p1.y;
        }
        s0 += __shfl_xor_sync(0xffffffffu, s0, 1);
        s0 += __shfl_xor_sync(0xffffffffu, s0, 2);
        s1 += __shfl_xor_sync(0xffffffffu, s1, 1);
        s1 += __shfl_xor_sync(0xffffffffu, s1, 2);
        if ((lane & 3) == 0) {
            atomicAdd(&g_rowsum[gr], s0);
            atomicAdd(&g_rowsum[gr + 8], s1);
        }
    }
}

// ---------------------------------------------------------------------------
// Kernel 4: softmax normalize codes (float4 elementwise)
// ---------------------------------------------------------------------------
__global__ void scale_kernel(float* __restrict__ codes) {
    size_t i = (size_t)blockIdx.x * blockDim.x + threadIdx.x;
    size_t r = i >> 10;
    float inv = 1.0f / g_rowsum[r];
    float4 v = ((float4*)codes)[i];
    v.x *= inv; v.y *= inv; v.z *= inv; v.w *= inv;
    ((float4*)codes)[i] = v;
}

// ---------------------------------------------------------------------------
// Kernel 5a: bow partial means. grid (128, 16), 64 threads.
// ---------------------------------------------------------------------------
__global__ __launch_bounds__(64) void bow_partial_kernel(
    const float* __restrict__ codes, float* __restrict__ bow)
{
    int n = blockIdx.x, kc = blockIdx.y, t = threadIdx.x;
    int col = kc * 256 + t * 4;
    float4 acc = make_float4(0.f, 0.f, 0.f, 0.f);
#pragma unroll 1
    for (int rr = 2; rr < 12; ++rr) {
#pragma unroll
        for (int cc = 2; cc < 12; ++cc) {
            int l = rr * 14 + cc;
            float4 v = *(const float4*)(codes + ((size_t)n * LTOK + l) * KCODES + col);
            acc.x += v.x; acc.y += v.y; acc.z += v.z; acc.w += v.w;
        }
    }
    acc.x *= 0.01f; acc.y *= 0.01f; acc.z *= 0.01f; acc.w *= 0.01f;
    *(float4*)(bow + (size_t)n * KCODES + col) = acc;
}

// ---------------------------------------------------------------------------
// Kernel 5b: L1-normalize bow rows.
// ---------------------------------------------------------------------------
__global__ __launch_bounds__(256) void bow_norm_kernel(float* __restrict__ bow) {
    int n = blockIdx.x, t = threadIdx.x;
    float4* row = (float4*)(bow + (size_t)n * KCODES);
    float4 v[4];
    float s = 0.0f;
#pragma unroll
    for (int j = 0; j < 4; ++j) {
        v[j] = row[t + j * 256];
        s += fabsf(v[j].x) + fabsf(v[j].y) + fabsf(v[j].z) + fabsf(v[j].w);
    }
    __shared__ float sred[256];
    sred[t] = s;
    __syncthreads();
    for (int o = 128; o > 0; o >>= 1) {
        if (t < o) sred[t] += sred[t + o];
        __syncthreads();
    }
    float inv = 1.0f / fmaxf(sred[0], NORM_EPS);
#pragma unroll
    for (int j = 0; j < 4; ++j) {
        v[j].x *= inv; v[j].y *= inv; v[j].z *= inv; v[j].w *= inv;
        row[t + j * 256] = v[j];
    }
}

// ---------------------------------------------------------------------------
// Launch
// ---------------------------------------------------------------------------
extern "C" void kernel_launch(void* const* d_in, const int* in_sizes, int n_in,
                              void* d_out, int out_size) {
    const float* x   = (const float*)d_in[0];
    const float* emb = (const float*)d_in[1];
    float* out_bow   = (float*)d_out;
    float* out_codes = (float*)d_out + (size_t)NBATCH * KCODES;

    cudaFuncSetAttribute(gemm_exp_kernel, cudaFuncAttributeMaxDynamicSharedMemorySize,
                         SMEM_GEMM);

    prep_x_kernel<<<MROWS * 32 / 256, 256>>>(x);
    conv_emb_kernel<<<(KCODES * CDIM / 4) / 256, 256>>>(emb);

    noop_kernel<<<1, 32>>>();   // keep ncu fixed sampling slot on the GEMM

    gemm_exp_kernel<<<dim3(KCODES / BN, MROWS / BM), GTHREADS, SMEM_GEMM>>>(out_codes);

    {
        size_t nf4 = (size_t)MROWS * KCODES / 4;
        scale_kernel<<<(int)(nf4 / 256), 256>>>(out_codes);
    }
    bow_partial_kernel<<<dim3(NBATCH, 16), 64>>>(out_codes, out_bow);
    bow_norm_kernel<<<NBATCH, 256>>>(out_bow);
}

// round 12
// speedup vs baseline: 5.8070x; 1.2751x over previous
#include <cuda_runtime.h>
#include <cuda_fp16.h>
#include <cstdint>
#include <math.h>

// ---------------------------------------------------------------------------
// Problem constants
// ---------------------------------------------------------------------------
#define NBATCH 128
#define LTOK   196
#define CDIM   768
#define KCODES 4096
#define MROWS  (NBATCH * LTOK)        // 25088
#define INV_DELTA_EFF 30.0f           // 15.0 / 0.5
#define NORM_EPS 1e-5f

// GEMM tiling (portable HMMA mma.sync path)
#define BM 128
#define BN 256
#define BK 32
#define NCHUNK (CDIM / BK)            // 24
#define GTHREADS 512                  // 16 warps: 4x4 grid, warp tile 32x64
#define NSTAGE 6

// smem rows: 32 halves data + 8 pad = 80 B per row (conflict-free ldmatrix)
#define ROWB 80
#define ABUF_BYTES (128 * ROWB)       // 10240 (A hi)
#define BBUF_BYTES (256 * ROWB)       // 20480 (B hi)
#define OFF_BHI ABUF_BYTES
#define STAGE_BYTES (ABUF_BYTES + BBUF_BYTES)           // 30720
#define SMEM_GEMM (NSTAGE * STAGE_BYTES)                // 184320

// ---------------------------------------------------------------------------
// Scratch
// ---------------------------------------------------------------------------
__device__ __half g_Ahi[(size_t)MROWS * CDIM];
__device__ __half g_Bhi[(size_t)KCODES * CDIM];
__device__ float  g_rowsum[MROWS];

// ---------------------------------------------------------------------------
// PTX helpers
// ---------------------------------------------------------------------------
__device__ __forceinline__ uint32_t smem_u32(const void* p) {
    uint32_t a;
    asm("{ .reg .u64 t; cvta.to.shared.u64 t, %1; cvt.u32.u64 %0, t; }" : "=r"(a) : "l"(p));
    return a;
}
#define CP_ASYNC16(dst, src) \
    asm volatile("cp.async.cg.shared.global [%0], [%1], 16;\n" :: "r"(dst), "l"(src))
#define CP_COMMIT() asm volatile("cp.async.commit_group;\n" ::: "memory")
#define CP_WAIT4()  asm volatile("cp.async.wait_group 4;\n" ::: "memory")
#define CP_WAIT3()  asm volatile("cp.async.wait_group 3;\n" ::: "memory")
#define CP_WAIT2()  asm volatile("cp.async.wait_group 2;\n" ::: "memory")
#define CP_WAIT1()  asm volatile("cp.async.wait_group 1;\n" ::: "memory")
#define CP_WAIT0()  asm volatile("cp.async.wait_group 0;\n" ::: "memory")

__device__ __forceinline__ void ldsm_x4(uint32_t* r, uint32_t addr) {
    asm volatile("ldmatrix.sync.aligned.m8n8.x4.shared.b16 {%0,%1,%2,%3}, [%4];"
                 : "=r"(r[0]), "=r"(r[1]), "=r"(r[2]), "=r"(r[3]) : "r"(addr));
}
__device__ __forceinline__ void mma16816(float* c, const uint32_t* a, uint32_t b0, uint32_t b1) {
    asm volatile("mma.sync.aligned.m16n8k16.row.col.f32.f16.f16.f32 "
                 "{%0,%1,%2,%3}, {%4,%5,%6,%7}, {%8,%9}, {%0,%1,%2,%3};"
                 : "+f"(c[0]), "+f"(c[1]), "+f"(c[2]), "+f"(c[3])
                 : "r"(a[0]), "r"(a[1]), "r"(a[2]), "r"(a[3]), "r"(b0), "r"(b1));
}

// ---------------------------------------------------------------------------
// Kernel 1: row inv-L2-norm; write fp16 of xn; zero rowsum.
// ---------------------------------------------------------------------------
__global__ void prep_x_kernel(const float* __restrict__ x) {
    int gw = (blockIdx.x * blockDim.x + threadIdx.x) >> 5;
    int lane = threadIdx.x & 31;
    if (gw >= MROWS) return;
    int n = gw / LTOK, l = gw % LTOK;
    const float4* r4 = (const float4*)(x + ((size_t)n * 197 + l + 1) * CDIM);

    float4 v[6];
    float s = 0.0f;
#pragma unroll
    for (int i = 0; i < 6; ++i) {
        v[i] = r4[lane + i * 32];
        s += v[i].x * v[i].x + v[i].y * v[i].y + v[i].z * v[i].z + v[i].w * v[i].w;
    }
#pragma unroll
    for (int o = 16; o > 0; o >>= 1) s += __shfl_xor_sync(0xffffffffu, s, o);
    float inv = 1.0f / fmaxf(sqrtf(s), NORM_EPS);

    uint2* ah = (uint2*)(g_Ahi + (size_t)gw * CDIM);
#pragma unroll
    for (int i = 0; i < 6; ++i) {
        __half h[4];
        h[0] = __float2half_rn(v[i].x * inv);
        h[1] = __float2half_rn(v[i].y * inv);
        h[2] = __float2half_rn(v[i].z * inv);
        h[3] = __float2half_rn(v[i].w * inv);
        ah[lane + i * 32] = *(uint2*)h;
    }
    if (lane == 0) g_rowsum[gw] = 0.0f;
}

// ---------------------------------------------------------------------------
// Kernel 2: embedding -> fp16.
// ---------------------------------------------------------------------------
__global__ void conv_emb_kernel(const float* __restrict__ emb) {
    size_t i = (size_t)blockIdx.x * blockDim.x + threadIdx.x;
    float4 e = ((const float4*)emb)[i];
    __half h[4];
    h[0] = __float2half_rn(e.x);
    h[1] = __float2half_rn(e.y);
    h[2] = __float2half_rn(e.z);
    h[3] = __float2half_rn(e.w);
    ((uint2*)g_Bhi)[i] = *(uint2*)h;
}

// No-op kernel: keeps ncu's fixed sampling slot on the GEMM.
__global__ void noop_kernel() {}

// ---------------------------------------------------------------------------
// Kernel 3: HMMA GEMM  d = ah·bh (pure fp16 operands, fp32 accum)
// + fused exp epilogue. CTA 128x256, 512 threads (16 warps, warp tile 32x64),
// 6-stage single-barrier cp.async pipeline. 6 ldsm per 16 HMMA.
// ---------------------------------------------------------------------------
__device__ __forceinline__ void load_stage(uint32_t stage_sb, int k0, int row0, int col0, int tid) {
    // A hi: 128 rows x 4 chunks = 512 chunks; 1 per thread
    {
        int row = tid >> 2, ch = tid & 3;
        const __half* src = g_Ahi + (size_t)(row0 + row) * CDIM + k0 + ch * 8;
        CP_ASYNC16(stage_sb + row * ROWB + ch * 16, src);
    }
    // B hi: 256 rows x 4 chunks = 1024 chunks; 2 per thread
#pragma unroll
    for (int j = 0; j < 2; ++j) {
        int c = tid * 2 + j;
        int row = c >> 2, ch = c & 3;
        const __half* src = g_Bhi + (size_t)(col0 + row) * CDIM + k0 + ch * 8;
        CP_ASYNC16(stage_sb + OFF_BHI + row * ROWB + ch * 16, src);
    }
    CP_COMMIT();
}

__global__ __launch_bounds__(GTHREADS, 1) void gemm_exp_kernel(float* __restrict__ codes) {
    extern __shared__ char smem[];
    const uint32_t sb = smem_u32(smem);
    const int tid  = threadIdx.x;
    const int lane = tid & 31;
    const int warp = tid >> 5;
    const int wm = warp >> 2;              // 0..3 (32-row stripes)
    const int wn = warp & 3;               // 0..3 (64-col stripes)
    const int row0 = blockIdx.y * BM;
    const int col0 = blockIdx.x * BN;

    const int lm = lane & 7;
    const int lg = lane >> 3;

    const int a_row = wm * 32 + lm + (lg & 1) * 8;      // + mf*16
    const int a_kk  = (lg >> 1) * 8;
    const int b_row = wn * 64 + lm + (lg >> 1) * 8;     // + nf2*16
    const int b_kk  = (lg & 1) * 8;

    float acc[2][8][4];
#pragma unroll
    for (int i = 0; i < 2; ++i)
#pragma unroll
        for (int j = 0; j < 8; ++j)
#pragma unroll
            for (int c = 0; c < 4; ++c) acc[i][j][c] = 0.0f;

    load_stage(sb + 0 * STAGE_BYTES, 0 * BK, row0, col0, tid);
    load_stage(sb + 1 * STAGE_BYTES, 1 * BK, row0, col0, tid);
    load_stage(sb + 2 * STAGE_BYTES, 2 * BK, row0, col0, tid);
    load_stage(sb + 3 * STAGE_BYTES, 3 * BK, row0, col0, tid);
    load_stage(sb + 4 * STAGE_BYTES, 4 * BK, row0, col0, tid);

    for (int i = 0; i < NCHUNK; ++i) {
        if (i < NCHUNK - 4)      { CP_WAIT4(); }
        else if (i == NCHUNK - 4){ CP_WAIT3(); }
        else if (i == NCHUNK - 3){ CP_WAIT2(); }
        else if (i == NCHUNK - 2){ CP_WAIT1(); }
        else                     { CP_WAIT0(); }
        __syncthreads();

        // Prefetch stage i+5 into the slot consumed in iteration i-1 (safe:
        // the barrier above guarantees all warps finished reading it).
        if (i + 5 < NCHUNK)
            load_stage(sb + ((i + 5) % NSTAGE) * STAGE_BYTES, (i + 5) * BK, row0, col0, tid);

        const uint32_t sA = sb + (i % NSTAGE) * STAGE_BYTES;
        const uint32_t sB = sA + OFF_BHI;

#pragma unroll
        for (int ks = 0; ks < 2; ++ks) {
            uint32_t aH[2][4];
#pragma unroll
            for (int mf = 0; mf < 2; ++mf) {
                uint32_t aoff = (uint32_t)((a_row + mf * 16) * ROWB + (ks * 16 + a_kk) * 2);
                ldsm_x4(aH[mf], sA + aoff);
            }
#pragma unroll
            for (int nf2 = 0; nf2 < 4; ++nf2) {
                uint32_t bH[4];
                uint32_t boff = (uint32_t)((b_row + nf2 * 16) * ROWB + (ks * 16 + b_kk) * 2);
                ldsm_x4(bH, sB + boff);
#pragma unroll
                for (int mf = 0; mf < 2; ++mf) {
                    mma16816(acc[mf][nf2 * 2 + 0], aH[mf], bH[0], bH[1]);
                    mma16816(acc[mf][nf2 * 2 + 1], aH[mf], bH[2], bH[3]);
                }
            }
        }
    }

    // Epilogue: p = exp(30*d - 30); coalesced v2 stores; rowsum atomics.
#pragma unroll
    for (int mf = 0; mf < 2; ++mf) {
        int gr = row0 + wm * 32 + mf * 16 + (lane >> 2);   // rows gr and gr+8
        float s0 = 0.0f, s1 = 0.0f;
#pragma unroll
        for (int nf = 0; nf < 8; ++nf) {
            float* c = acc[mf][nf];
            float2 p0, p1;
            p0.x = __expf(fmaf(INV_DELTA_EFF, c[0], -INV_DELTA_EFF));
            p0.y = __expf(fmaf(INV_DELTA_EFF, c[1], -INV_DELTA_EFF));
            p1.x = __expf(fmaf(INV_DELTA_EFF, c[2], -INV_DELTA_EFF));
            p1.y = __expf(fmaf(INV_DELTA_EFF, c[3], -INV_DELTA_EFF));
            int gc = col0 + wn * 64 + nf * 8 + (lane & 3) * 2;
            *(float2*)(codes + (size_t)gr * KCODES + gc)       = p0;
            *(float2*)(codes + (size_t)(gr + 8) * KCODES + gc) = p1;
            s0 += p0.x + p0.y;
            s1 += p1.x + p1.y;
        }
        s0 += __shfl_xor_sync(0xffffffffu, s0, 1);
        s0 += __shfl_xor_sync(0xffffffffu, s0, 2);
        s1 += __shfl_xor_sync(0xffffffffu, s1, 1);
        s1 += __shfl_xor_sync(0xffffffffu, s1, 2);
        if ((lane & 3) == 0) {
            atomicAdd(&g_rowsum[gr], s0);
            atomicAdd(&g_rowsum[gr + 8], s1);
        }
    }
}

// ---------------------------------------------------------------------------
// Kernel 4: softmax normalize codes (float4 elementwise)
// ---------------------------------------------------------------------------
__global__ void scale_kernel(float* __restrict__ codes) {
    size_t i = (size_t)blockIdx.x * blockDim.x + threadIdx.x;
    size_t r = i >> 10;
    float inv = 1.0f / g_rowsum[r];
    float4 v = ((float4*)codes)[i];
    v.x *= inv; v.y *= inv; v.z *= inv; v.w *= inv;
    ((float4*)codes)[i] = v;
}

// ---------------------------------------------------------------------------
// Kernel 5a: bow partial means. grid (128, 16), 64 threads.
// ---------------------------------------------------------------------------
__global__ __launch_bounds__(64) void bow_partial_kernel(
    const float* __restrict__ codes, float* __restrict__ bow)
{
    int n = blockIdx.x, kc = blockIdx.y, t = threadIdx.x;
    int col = kc * 256 + t * 4;
    float4 acc = make_float4(0.f, 0.f, 0.f, 0.f);
#pragma unroll 1
    for (int rr = 2; rr < 12; ++rr) {
#pragma unroll
        for (int cc = 2; cc < 12; ++cc) {
            int l = rr * 14 + cc;
            float4 v = *(const float4*)(codes + ((size_t)n * LTOK + l) * KCODES + col);
            acc.x += v.x; acc.y += v.y; acc.z += v.z; acc.w += v.w;
        }
    }
    acc.x *= 0.01f; acc.y *= 0.01f; acc.z *= 0.01f; acc.w *= 0.01f;
    *(float4*)(bow + (size_t)n * KCODES + col) = acc;
}

// ---------------------------------------------------------------------------
// Kernel 5b: L1-normalize bow rows.
// ---------------------------------------------------------------------------
__global__ __launch_bounds__(256) void bow_norm_kernel(float* __restrict__ bow) {
    int n = blockIdx.x, t = threadIdx.x;
    float4* row = (float4*)(bow + (size_t)n * KCODES);
    float4 v[4];
    float s = 0.0f;
#pragma unroll
    for (int j = 0; j < 4; ++j) {
        v[j] = row[t + j * 256];
        s += fabsf(v[j].x) + fabsf(v[j].y) + fabsf(v[j].z) + fabsf(v[j].w);
    }
    __shared__ float sred[256];
    sred[t] = s;
    __syncthreads();
    for (int o = 128; o > 0; o >>= 1) {
        if (t < o) sred[t] += sred[t + o];
        __syncthreads();
    }
    float inv = 1.0f / fmaxf(sred[0], NORM_EPS);
#pragma unroll
    for (int j = 0; j < 4; ++j) {
        v[j].x *= inv; v[j].y *= inv; v[j].z *= inv; v[j].w *= inv;
        row[t + j * 256] = v[j];
    }
}

// ---------------------------------------------------------------------------
// Launch
// ---------------------------------------------------------------------------
extern "C" void kernel_launch(void* const* d_in, const int* in_sizes, int n_in,
                              void* d_out, int out_size) {
    const float* x   = (const float*)d_in[0];
    const float* emb = (const float*)d_in[1];
    float* out_bow   = (float*)d_out;
    float* out_codes = (float*)d_out + (size_t)NBATCH * KCODES;

    cudaFuncSetAttribute(gemm_exp_kernel, cudaFuncAttributeMaxDynamicSharedMemorySize,
                         SMEM_GEMM);

    prep_x_kernel<<<MROWS * 32 / 256, 256>>>(x);
    conv_emb_kernel<<<(KCODES * CDIM / 4) / 256, 256>>>(emb);

    noop_kernel<<<1, 32>>>();   // keep ncu fixed sampling slot on the GEMM

    gemm_exp_kernel<<<dim3(KCODES / BN, MROWS / BM), GTHREADS, SMEM_GEMM>>>(out_codes);

    {
        size_t nf4 = (size_t)MROWS * KCODES / 4;
        scale_kernel<<<(int)(nf4 / 256), 256>>>(out_codes);
    }
    bow_partial_kernel<<<dim3(NBATCH, 16), 64>>>(out_codes, out_bow);
    bow_norm_kernel<<<NBATCH, 256>>>(out_bow);
}

// round 13
// speedup vs baseline: 6.3194x; 1.0883x over previous
#include <cuda_runtime.h>
#include <cuda_fp16.h>
#include <cstdint>
#include <math.h>

// ---------------------------------------------------------------------------
// Problem constants
// ---------------------------------------------------------------------------
#define NBATCH 128
#define LTOK   196
#define CDIM   768
#define KCODES 4096
#define MROWS  (NBATCH * LTOK)        // 25088
#define INV_DELTA_EFF 30.0f           // 15.0 / 0.5
#define NORM_EPS 1e-5f

// GEMM tiling (portable HMMA mma.sync path)
#define BM 128
#define BN 128
#define BK 32
#define NCHUNK (CDIM / BK)            // 24
#define GTHREADS 256                  // 8 warps: 4x2 grid, warp tile 32x64
#define NSTAGE 5

// smem rows: 32 halves data + 8 pad = 80 B per row (conflict-free ldmatrix)
#define ROWB 80
#define ABUF_BYTES (128 * ROWB)       // 10240 (A)
#define BBUF_BYTES (128 * ROWB)       // 10240 (B)
#define OFF_BHI ABUF_BYTES
#define STAGE_BYTES (ABUF_BYTES + BBUF_BYTES)           // 20480
#define SMEM_GEMM (NSTAGE * STAGE_BYTES)                // 102400 -> 2 CTAs/SM

// ---------------------------------------------------------------------------
// Scratch
// ---------------------------------------------------------------------------
__device__ __half g_Ahi[(size_t)MROWS * CDIM];
__device__ __half g_Bhi[(size_t)KCODES * CDIM];
__device__ float  g_rowsum[MROWS];

// ---------------------------------------------------------------------------
// PTX helpers
// ---------------------------------------------------------------------------
__device__ __forceinline__ uint32_t smem_u32(const void* p) {
    uint32_t a;
    asm("{ .reg .u64 t; cvta.to.shared.u64 t, %1; cvt.u32.u64 %0, t; }" : "=r"(a) : "l"(p));
    return a;
}
#define CP_ASYNC16(dst, src) \
    asm volatile("cp.async.cg.shared.global [%0], [%1], 16;\n" :: "r"(dst), "l"(src))
#define CP_COMMIT() asm volatile("cp.async.commit_group;\n" ::: "memory")
#define CP_WAIT3()  asm volatile("cp.async.wait_group 3;\n" ::: "memory")
#define CP_WAIT2()  asm volatile("cp.async.wait_group 2;\n" ::: "memory")
#define CP_WAIT1()  asm volatile("cp.async.wait_group 1;\n" ::: "memory")
#define CP_WAIT0()  asm volatile("cp.async.wait_group 0;\n" ::: "memory")

__device__ __forceinline__ void ldsm_x4(uint32_t* r, uint32_t addr) {
    asm volatile("ldmatrix.sync.aligned.m8n8.x4.shared.b16 {%0,%1,%2,%3}, [%4];"
                 : "=r"(r[0]), "=r"(r[1]), "=r"(r[2]), "=r"(r[3]) : "r"(addr));
}
__device__ __forceinline__ void mma16816(float* c, const uint32_t* a, uint32_t b0, uint32_t b1) {
    asm volatile("mma.sync.aligned.m16n8k16.row.col.f32.f16.f16.f32 "
                 "{%0,%1,%2,%3}, {%4,%5,%6,%7}, {%8,%9}, {%0,%1,%2,%3};"
                 : "+f"(c[0]), "+f"(c[1]), "+f"(c[2]), "+f"(c[3])
                 : "r"(a[0]), "r"(a[1]), "r"(a[2]), "r"(a[3]), "r"(b0), "r"(b1));
}

// ---------------------------------------------------------------------------
// Kernel 1: row inv-L2-norm; write fp16 of xn; zero rowsum.
// ---------------------------------------------------------------------------
__global__ void prep_x_kernel(const float* __restrict__ x) {
    int gw = (blockIdx.x * blockDim.x + threadIdx.x) >> 5;
    int lane = threadIdx.x & 31;
    if (gw >= MROWS) return;
    int n = gw / LTOK, l = gw % LTOK;
    const float4* r4 = (const float4*)(x + ((size_t)n * 197 + l + 1) * CDIM);

    float4 v[6];
    float s = 0.0f;
#pragma unroll
    for (int i = 0; i < 6; ++i) {
        v[i] = r4[lane + i * 32];
        s += v[i].x * v[i].x + v[i].y * v[i].y + v[i].z * v[i].z + v[i].w * v[i].w;
    }
#pragma unroll
    for (int o = 16; o > 0; o >>= 1) s += __shfl_xor_sync(0xffffffffu, s, o);
    float inv = 1.0f / fmaxf(sqrtf(s), NORM_EPS);

    uint2* ah = (uint2*)(g_Ahi + (size_t)gw * CDIM);
#pragma unroll
    for (int i = 0; i < 6; ++i) {
        __half h[4];
        h[0] = __float2half_rn(v[i].x * inv);
        h[1] = __float2half_rn(v[i].y * inv);
        h[2] = __float2half_rn(v[i].z * inv);
        h[3] = __float2half_rn(v[i].w * inv);
        ah[lane + i * 32] = *(uint2*)h;
    }
    if (lane == 0) g_rowsum[gw] = 0.0f;
}

// ---------------------------------------------------------------------------
// Kernel 2: embedding -> fp16.
// ---------------------------------------------------------------------------
__global__ void conv_emb_kernel(const float* __restrict__ emb) {
    size_t i = (size_t)blockIdx.x * blockDim.x + threadIdx.x;
    float4 e = ((const float4*)emb)[i];
    __half h[4];
    h[0] = __float2half_rn(e.x);
    h[1] = __float2half_rn(e.y);
    h[2] = __float2half_rn(e.z);
    h[3] = __float2half_rn(e.w);
    ((uint2*)g_Bhi)[i] = *(uint2*)h;
}

// No-op kernel: keeps ncu's fixed sampling slot on the GEMM.
__global__ void noop_kernel() {}

// ---------------------------------------------------------------------------
// Kernel 3: HMMA GEMM  d = ah·bh + fused exp epilogue.
// CTA 128x128, 256 threads (8 warps, warp tile 32x64), 5-stage pipeline,
// 2 CTAs/SM co-resident (launch_bounds(256,2) -> 128-reg cap) so barrier and
// epilogue stalls of one CTA are covered by the other's MMA issue.
// ---------------------------------------------------------------------------
__device__ __forceinline__ void load_stage(uint32_t stage_sb, int k0, int row0, int col0, int tid) {
    // A: 128 rows x 4 chunks = 512; 2 per thread
#pragma unroll
    for (int j = 0; j < 2; ++j) {
        int c = tid * 2 + j;
        int row = c >> 2, ch = c & 3;
        const __half* src = g_Ahi + (size_t)(row0 + row) * CDIM + k0 + ch * 8;
        CP_ASYNC16(stage_sb + row * ROWB + ch * 16, src);
    }
    // B: 128 rows x 4 chunks = 512; 2 per thread
#pragma unroll
    for (int j = 0; j < 2; ++j) {
        int c = tid * 2 + j;
        int row = c >> 2, ch = c & 3;
        const __half* src = g_Bhi + (size_t)(col0 + row) * CDIM + k0 + ch * 8;
        CP_ASYNC16(stage_sb + OFF_BHI + row * ROWB + ch * 16, src);
    }
    CP_COMMIT();
}

__global__ __launch_bounds__(GTHREADS, 2) void gemm_exp_kernel(float* __restrict__ codes) {
    extern __shared__ char smem[];
    const uint32_t sb = smem_u32(smem);
    const int tid  = threadIdx.x;
    const int lane = tid & 31;
    const int warp = tid >> 5;
    const int wm = warp >> 1;              // 0..3 (32-row stripes)
    const int wn = warp & 1;               // 0..1 (64-col stripes)
    const int row0 = blockIdx.y * BM;
    const int col0 = blockIdx.x * BN;

    const int lm = lane & 7;
    const int lg = lane >> 3;

    const int a_row = wm * 32 + lm + (lg & 1) * 8;      // + mf*16
    const int a_kk  = (lg >> 1) * 8;
    const int b_row = wn * 64 + lm + (lg >> 1) * 8;     // + nf2*16
    const int b_kk  = (lg & 1) * 8;

    float acc[2][8][4];
#pragma unroll
    for (int i = 0; i < 2; ++i)
#pragma unroll
        for (int j = 0; j < 8; ++j)
#pragma unroll
            for (int c = 0; c < 4; ++c) acc[i][j][c] = 0.0f;

    load_stage(sb + 0 * STAGE_BYTES, 0 * BK, row0, col0, tid);
    load_stage(sb + 1 * STAGE_BYTES, 1 * BK, row0, col0, tid);
    load_stage(sb + 2 * STAGE_BYTES, 2 * BK, row0, col0, tid);
    load_stage(sb + 3 * STAGE_BYTES, 3 * BK, row0, col0, tid);

    for (int i = 0; i < NCHUNK; ++i) {
        if (i < NCHUNK - 3)      { CP_WAIT3(); }
        else if (i == NCHUNK - 3){ CP_WAIT2(); }
        else if (i == NCHUNK - 2){ CP_WAIT1(); }
        else                     { CP_WAIT0(); }
        __syncthreads();

        // Prefetch stage i+4 into the slot consumed in iteration i-1 (safe:
        // the barrier above guarantees all warps finished reading it).
        if (i + 4 < NCHUNK)
            load_stage(sb + ((i + 4) % NSTAGE) * STAGE_BYTES, (i + 4) * BK, row0, col0, tid);

        const uint32_t sA = sb + (i % NSTAGE) * STAGE_BYTES;
        const uint32_t sB = sA + OFF_BHI;

#pragma unroll
        for (int ks = 0; ks < 2; ++ks) {
            uint32_t aH[2][4];
#pragma unroll
            for (int mf = 0; mf < 2; ++mf) {
                uint32_t aoff = (uint32_t)((a_row + mf * 16) * ROWB + (ks * 16 + a_kk) * 2);
                ldsm_x4(aH[mf], sA + aoff);
            }
#pragma unroll
            for (int nf2 = 0; nf2 < 4; ++nf2) {
                uint32_t bH[4];
                uint32_t boff = (uint32_t)((b_row + nf2 * 16) * ROWB + (ks * 16 + b_kk) * 2);
                ldsm_x4(bH, sB + boff);
#pragma unroll
                for (int mf = 0; mf < 2; ++mf) {
                    mma16816(acc[mf][nf2 * 2 + 0], aH[mf], bH[0], bH[1]);
                    mma16816(acc[mf][nf2 * 2 + 1], aH[mf], bH[2], bH[3]);
                }
            }
        }
    }

    // Epilogue: p = exp(30*d - 30); coalesced v2 stores; rowsum atomics.
#pragma unroll
    for (int mf = 0; mf < 2; ++mf) {
        int gr = row0 + wm * 32 + mf * 16 + (lane >> 2);   // rows gr and gr+8
        float s0 = 0.0f, s1 = 0.0f;
#pragma unroll
        for (int nf = 0; nf < 8; ++nf) {
            float* c = acc[mf][nf];
            float2 p0, p1;
            p0.x = __expf(fmaf(INV_DELTA_EFF, c[0], -INV_DELTA_EFF));
            p0.y = __expf(fmaf(INV_DELTA_EFF, c[1], -INV_DELTA_EFF));
            p1.x = __expf(fmaf(INV_DELTA_EFF, c[2], -INV_DELTA_EFF));
            p1.y = __expf(fmaf(INV_DELTA_EFF, c[3], -INV_DELTA_EFF));
            int gc = col0 + wn * 64 + nf * 8 + (lane & 3) * 2;
            *(float2*)(codes + (size_t)gr * KCODES + gc)       = p0;
            *(float2*)(codes + (size_t)(gr + 8) * KCODES + gc) = p1;
            s0 += p0.x + p0.y;
            s1 += p1.x + p1.y;
        }
        s0 += __shfl_xor_sync(0xffffffffu, s0, 1);
        s0 += __shfl_xor_sync(0xffffffffu, s0, 2);
        s1 += __shfl_xor_sync(0xffffffffu, s1, 1);
        s1 += __shfl_xor_sync(0xffffffffu, s1, 2);
        if ((lane & 3) == 0) {
            atomicAdd(&g_rowsum[gr], s0);
            atomicAdd(&g_rowsum[gr + 8], s1);
        }
    }
}

// ---------------------------------------------------------------------------
// Kernel 4: softmax normalize codes (float4 elementwise)
// ---------------------------------------------------------------------------
__global__ void scale_kernel(float* __restrict__ codes) {
    size_t i = (size_t)blockIdx.x * blockDim.x + threadIdx.x;
    size_t r = i >> 10;
    float inv = 1.0f / g_rowsum[r];
    float4 v = ((float4*)codes)[i];
    v.x *= inv; v.y *= inv; v.z *= inv; v.w *= inv;
    ((float4*)codes)[i] = v;
}

// ---------------------------------------------------------------------------
// Kernel 5a: bow partial means. grid (128, 16), 64 threads.
// ---------------------------------------------------------------------------
__global__ __launch_bounds__(64) void bow_partial_kernel(
    const float* __restrict__ codes, float* __restrict__ bow)
{
    int n = blockIdx.x, kc = blockIdx.y, t = threadIdx.x;
    int col = kc * 256 + t * 4;
    float4 acc = make_float4(0.f, 0.f, 0.f, 0.f);
#pragma unroll 1
    for (int rr = 2; rr < 12; ++rr) {
#pragma unroll
        for (int cc = 2; cc < 12; ++cc) {
            int l = rr * 14 + cc;
            float4 v = *(const float4*)(codes + ((size_t)n * LTOK + l) * KCODES + col);
            acc.x += v.x; acc.y += v.y; acc.z += v.z; acc.w += v.w;
        }
    }
    acc.x *= 0.01f; acc.y *= 0.01f; acc.z *= 0.01f; acc.w *= 0.01f;
    *(float4*)(bow + (size_t)n * KCODES + col) = acc;
}

// ---------------------------------------------------------------------------
// Kernel 5b: L1-normalize bow rows.
// ---------------------------------------------------------------------------
__global__ __launch_bounds__(256) void bow_norm_kernel(float* __restrict__ bow) {
    int n = blockIdx.x, t = threadIdx.x;
    float4* row = (float4*)(bow + (size_t)n * KCODES);
    float4 v[4];
    float s = 0.0f;
#pragma unroll
    for (int j = 0; j < 4; ++j) {
        v[j] = row[t + j * 256];
        s += fabsf(v[j].x) + fabsf(v[j].y) + fabsf(v[j].z) + fabsf(v[j].w);
    }
    __shared__ float sred[256];
    sred[t] = s;
    __syncthreads();
    for (int o = 128; o > 0; o >>= 1) {
        if (t < o) sred[t] += sred[t + o];
        __syncthreads();
    }
    float inv = 1.0f / fmaxf(sred[0], NORM_EPS);
#pragma unroll
    for (int j = 0; j < 4; ++j) {
        v[j].x *= inv; v[j].y *= inv; v[j].z *= inv; v[j].w *= inv;
        row[t + j * 256] = v[j];
    }
}

// ---------------------------------------------------------------------------
// Launch
// ---------------------------------------------------------------------------
extern "C" void kernel_launch(void* const* d_in, const int* in_sizes, int n_in,
                              void* d_out, int out_size) {
    const float* x   = (const float*)d_in[0];
    const float* emb = (const float*)d_in[1];
    float* out_bow   = (float*)d_out;
    float* out_codes = (float*)d_out + (size_t)NBATCH * KCODES;

    cudaFuncSetAttribute(gemm_exp_kernel, cudaFuncAttributeMaxDynamicSharedMemorySize,
                         SMEM_GEMM);

    prep_x_kernel<<<MROWS * 32 / 256, 256>>>(x);
    conv_emb_kernel<<<(KCODES * CDIM / 4) / 256, 256>>>(emb);

    noop_kernel<<<1, 32>>>();   // keep ncu fixed sampling slot on the GEMM

    gemm_exp_kernel<<<dim3(KCODES / BN, MROWS / BM), GTHREADS, SMEM_GEMM>>>(out_codes);

    {
        size_t nf4 = (size_t)MROWS * KCODES / 4;
        scale_kernel<<<(int)(nf4 / 256), 256>>>(out_codes);
    }
    bow_partial_kernel<<<dim3(NBATCH, 16), 64>>>(out_codes, out_bow);
    bow_norm_kernel<<<NBATCH, 256>>>(out_bow);
}

// round 14
// speedup vs baseline: 7.2317x; 1.1444x over previous
#include <cuda_runtime.h>
#include <cuda_fp16.h>
#include <cstdint>
#include <math.h>

// ---------------------------------------------------------------------------
// Problem constants
// ---------------------------------------------------------------------------
#define NBATCH 128
#define LTOK   196
#define CDIM   768
#define KCODES 4096
#define MROWS  (NBATCH * LTOK)        // 25088
#define INV_DELTA_EFF 30.0f           // 15.0 / 0.5
#define NORM_EPS 1e-5f

// GEMM tiling (portable HMMA mma.sync path)
#define BM 128
#define BN 128
#define BK 32
#define NCHUNK (CDIM / BK)            // 24
#define GTHREADS 512                  // 16 warps: 4x4 grid, warp tile 32x32
#define NSTAGE 5

// smem rows: 32 halves data + 8 pad = 80 B per row (conflict-free ldmatrix)
#define ROWB 80
#define ABUF_BYTES (128 * ROWB)       // 10240 (A)
#define BBUF_BYTES (128 * ROWB)       // 10240 (B)
#define OFF_BHI ABUF_BYTES
#define STAGE_BYTES (ABUF_BYTES + BBUF_BYTES)           // 20480
#define SMEM_GEMM (NSTAGE * STAGE_BYTES)                // 102400 -> 2 CTAs/SM

// ---------------------------------------------------------------------------
// Scratch
// ---------------------------------------------------------------------------
__device__ __half g_Ahi[(size_t)MROWS * CDIM];
__device__ __half g_Bhi[(size_t)KCODES * CDIM];
__device__ float  g_rowsum[MROWS];

// ---------------------------------------------------------------------------
// PTX helpers
// ---------------------------------------------------------------------------
__device__ __forceinline__ uint32_t smem_u32(const void* p) {
    uint32_t a;
    asm("{ .reg .u64 t; cvta.to.shared.u64 t, %1; cvt.u32.u64 %0, t; }" : "=r"(a) : "l"(p));
    return a;
}
#define CP_ASYNC16(dst, src) \
    asm volatile("cp.async.cg.shared.global [%0], [%1], 16;\n" :: "r"(dst), "l"(src))
#define CP_COMMIT() asm volatile("cp.async.commit_group;\n" ::: "memory")
#define CP_WAIT3()  asm volatile("cp.async.wait_group 3;\n" ::: "memory")
#define CP_WAIT2()  asm volatile("cp.async.wait_group 2;\n" ::: "memory")
#define CP_WAIT1()  asm volatile("cp.async.wait_group 1;\n" ::: "memory")
#define CP_WAIT0()  asm volatile("cp.async.wait_group 0;\n" ::: "memory")

__device__ __forceinline__ void ldsm_x4(uint32_t* r, uint32_t addr) {
    asm volatile("ldmatrix.sync.aligned.m8n8.x4.shared.b16 {%0,%1,%2,%3}, [%4];"
                 : "=r"(r[0]), "=r"(r[1]), "=r"(r[2]), "=r"(r[3]) : "r"(addr));
}
__device__ __forceinline__ void mma16816(float* c, const uint32_t* a, uint32_t b0, uint32_t b1) {
    asm volatile("mma.sync.aligned.m16n8k16.row.col.f32.f16.f16.f32 "
                 "{%0,%1,%2,%3}, {%4,%5,%6,%7}, {%8,%9}, {%0,%1,%2,%3};"
                 : "+f"(c[0]), "+f"(c[1]), "+f"(c[2]), "+f"(c[3])
                 : "r"(a[0]), "r"(a[1]), "r"(a[2]), "r"(a[3]), "r"(b0), "r"(b1));
}

// ---------------------------------------------------------------------------
// Kernel 1: row inv-L2-norm; write fp16 of xn; zero rowsum.
// ---------------------------------------------------------------------------
__global__ void prep_x_kernel(const float* __restrict__ x) {
    int gw = (blockIdx.x * blockDim.x + threadIdx.x) >> 5;
    int lane = threadIdx.x & 31;
    if (gw >= MROWS) return;
    int n = gw / LTOK, l = gw % LTOK;
    const float4* r4 = (const float4*)(x + ((size_t)n * 197 + l + 1) * CDIM);

    float4 v[6];
    float s = 0.0f;
#pragma unroll
    for (int i = 0; i < 6; ++i) {
        v[i] = r4[lane + i * 32];
        s += v[i].x * v[i].x + v[i].y * v[i].y + v[i].z * v[i].z + v[i].w * v[i].w;
    }
#pragma unroll
    for (int o = 16; o > 0; o >>= 1) s += __shfl_xor_sync(0xffffffffu, s, o);
    float inv = 1.0f / fmaxf(sqrtf(s), NORM_EPS);

    uint2* ah = (uint2*)(g_Ahi + (size_t)gw * CDIM);
#pragma unroll
    for (int i = 0; i < 6; ++i) {
        __half h[4];
        h[0] = __float2half_rn(v[i].x * inv);
        h[1] = __float2half_rn(v[i].y * inv);
        h[2] = __float2half_rn(v[i].z * inv);
        h[3] = __float2half_rn(v[i].w * inv);
        ah[lane + i * 32] = *(uint2*)h;
    }
    if (lane == 0) g_rowsum[gw] = 0.0f;
}

// ---------------------------------------------------------------------------
// Kernel 2: embedding -> fp16.
// ---------------------------------------------------------------------------
__global__ void conv_emb_kernel(const float* __restrict__ emb) {
    size_t i = (size_t)blockIdx.x * blockDim.x + threadIdx.x;
    float4 e = ((const float4*)emb)[i];
    __half h[4];
    h[0] = __float2half_rn(e.x);
    h[1] = __float2half_rn(e.y);
    h[2] = __float2half_rn(e.z);
    h[3] = __float2half_rn(e.w);
    ((uint2*)g_Bhi)[i] = *(uint2*)h;
}

// No-op kernel: keeps ncu's fixed sampling slot on the GEMM.
__global__ void noop_kernel() {}

// ---------------------------------------------------------------------------
// Kernel 3: HMMA GEMM  d = ah·bh + fused exp epilogue.
// CTA 128x128, 512 threads (16 warps, warp tile 32x32), 5-stage pipeline,
// 2 CTAs/SM co-resident (launch_bounds(512,2) -> 64-reg cap, acc=32 floats)
// = 32 warps/SM to fill the HMMA pipe (rt~8cyc) past the stall gaps.
// ---------------------------------------------------------------------------
__device__ __forceinline__ void load_stage(uint32_t stage_sb, int k0, int row0, int col0, int tid) {
    // A: 128 rows x 4 chunks = 512; 1 per thread
    {
        int row = tid >> 2, ch = tid & 3;
        const __half* src = g_Ahi + (size_t)(row0 + row) * CDIM + k0 + ch * 8;
        CP_ASYNC16(stage_sb + row * ROWB + ch * 16, src);
    }
    // B: 128 rows x 4 chunks = 512; 1 per thread
    {
        int row = tid >> 2, ch = tid & 3;
        const __half* src = g_Bhi + (size_t)(col0 + row) * CDIM + k0 + ch * 8;
        CP_ASYNC16(stage_sb + OFF_BHI + row * ROWB + ch * 16, src);
    }
    CP_COMMIT();
}

__global__ __launch_bounds__(GTHREADS, 2) void gemm_exp_kernel(float* __restrict__ codes) {
    extern __shared__ char smem[];
    const uint32_t sb = smem_u32(smem);
    const int tid  = threadIdx.x;
    const int lane = tid & 31;
    const int warp = tid >> 5;
    const int wm = warp >> 2;              // 0..3 (32-row stripes)
    const int wn = warp & 3;               // 0..3 (32-col stripes)
    const int row0 = blockIdx.y * BM;
    const int col0 = blockIdx.x * BN;

    const int lm = lane & 7;
    const int lg = lane >> 3;

    const int a_row = wm * 32 + lm + (lg & 1) * 8;      // + mf*16
    const int a_kk  = (lg >> 1) * 8;
    const int b_row = wn * 32 + lm + (lg >> 1) * 8;     // + nf2*16
    const int b_kk  = (lg & 1) * 8;

    float acc[2][4][4];
#pragma unroll
    for (int i = 0; i < 2; ++i)
#pragma unroll
        for (int j = 0; j < 4; ++j)
#pragma unroll
            for (int c = 0; c < 4; ++c) acc[i][j][c] = 0.0f;

    load_stage(sb + 0 * STAGE_BYTES, 0 * BK, row0, col0, tid);
    load_stage(sb + 1 * STAGE_BYTES, 1 * BK, row0, col0, tid);
    load_stage(sb + 2 * STAGE_BYTES, 2 * BK, row0, col0, tid);
    load_stage(sb + 3 * STAGE_BYTES, 3 * BK, row0, col0, tid);

    for (int i = 0; i < NCHUNK; ++i) {
        if (i < NCHUNK - 3)      { CP_WAIT3(); }
        else if (i == NCHUNK - 3){ CP_WAIT2(); }
        else if (i == NCHUNK - 2){ CP_WAIT1(); }
        else                     { CP_WAIT0(); }
        __syncthreads();

        // Prefetch stage i+4 into the slot consumed in iteration i-1 (safe:
        // the barrier above guarantees all warps finished reading it).
        if (i + 4 < NCHUNK)
            load_stage(sb + ((i + 4) % NSTAGE) * STAGE_BYTES, (i + 4) * BK, row0, col0, tid);

        const uint32_t sA = sb + (i % NSTAGE) * STAGE_BYTES;
        const uint32_t sB = sA + OFF_BHI;

#pragma unroll
        for (int ks = 0; ks < 2; ++ks) {
            uint32_t aH[2][4], bH[2][4];
#pragma unroll
            for (int mf = 0; mf < 2; ++mf) {
                uint32_t aoff = (uint32_t)((a_row + mf * 16) * ROWB + (ks * 16 + a_kk) * 2);
                ldsm_x4(aH[mf], sA + aoff);
            }
#pragma unroll
            for (int nf2 = 0; nf2 < 2; ++nf2) {
                uint32_t boff = (uint32_t)((b_row + nf2 * 16) * ROWB + (ks * 16 + b_kk) * 2);
                ldsm_x4(bH[nf2], sB + boff);
            }
#pragma unroll
            for (int nf2 = 0; nf2 < 2; ++nf2) {
#pragma unroll
                for (int mf = 0; mf < 2; ++mf) {
                    mma16816(acc[mf][nf2 * 2 + 0], aH[mf], bH[nf2][0], bH[nf2][1]);
                    mma16816(acc[mf][nf2 * 2 + 1], aH[mf], bH[nf2][2], bH[nf2][3]);
                }
            }
        }
    }

    // Epilogue: p = exp(30*d - 30); coalesced v2 stores; rowsum atomics.
#pragma unroll
    for (int mf = 0; mf < 2; ++mf) {
        int gr = row0 + wm * 32 + mf * 16 + (lane >> 2);   // rows gr and gr+8
        float s0 = 0.0f, s1 = 0.0f;
#pragma unroll
        for (int nf = 0; nf < 4; ++nf) {
            float* c = acc[mf][nf];
            float2 p0, p1;
            p0.x = __expf(fmaf(INV_DELTA_EFF, c[0], -INV_DELTA_EFF));
            p0.y = __expf(fmaf(INV_DELTA_EFF, c[1], -INV_DELTA_EFF));
            p1.x = __expf(fmaf(INV_DELTA_EFF, c[2], -INV_DELTA_EFF));
            p1.y = __expf(fmaf(INV_DELTA_EFF, c[3], -INV_DELTA_EFF));
            int gc = col0 + wn * 32 + nf * 8 + (lane & 3) * 2;
            *(float2*)(codes + (size_t)gr * KCODES + gc)       = p0;
            *(float2*)(codes + (size_t)(gr + 8) * KCODES + gc) = p1;
            s0 += p0.x + p0.y;
            s1 += p1.x + p1.y;
        }
        s0 += __shfl_xor_sync(0xffffffffu, s0, 1);
        s0 += __shfl_xor_sync(0xffffffffu, s0, 2);
        s1 += __shfl_xor_sync(0xffffffffu, s1, 1);
        s1 += __shfl_xor_sync(0xffffffffu, s1, 2);
        if ((lane & 3) == 0) {
            atomicAdd(&g_rowsum[gr], s0);
            atomicAdd(&g_rowsum[gr + 8], s1);
        }
    }
}

// ---------------------------------------------------------------------------
// Kernel 4: softmax normalize. One block per row; 4 float4 per thread;
// reciprocal hoisted (one load + MUFU per thread).
// ---------------------------------------------------------------------------
__global__ __launch_bounds__(256) void scale_kernel(float* __restrict__ codes) {
    int r = blockIdx.x;
    float inv = 1.0f / g_rowsum[r];
    float4* row = (float4*)(codes + (size_t)r * KCODES);
    int t = threadIdx.x;
#pragma unroll
    for (int j = 0; j < 4; ++j) {
        float4 v = row[t + j * 256];
        v.x *= inv; v.y *= inv; v.z *= inv; v.w *= inv;
        row[t + j * 256] = v;
    }
}

// ---------------------------------------------------------------------------
// Kernel 5a: bow partial means. grid (128, 16), 64 threads.
// ---------------------------------------------------------------------------
__global__ __launch_bounds__(64) void bow_partial_kernel(
    const float* __restrict__ codes, float* __restrict__ bow)
{
    int n = blockIdx.x, kc = blockIdx.y, t = threadIdx.x;
    int col = kc * 256 + t * 4;
    float4 acc = make_float4(0.f, 0.f, 0.f, 0.f);
#pragma unroll 1
    for (int rr = 2; rr < 12; ++rr) {
#pragma unroll
        for (int cc = 2; cc < 12; ++cc) {
            int l = rr * 14 + cc;
            float4 v = *(const float4*)(codes + ((size_t)n * LTOK + l) * KCODES + col);
            acc.x += v.x; acc.y += v.y; acc.z += v.z; acc.w += v.w;
        }
    }
    acc.x *= 0.01f; acc.y *= 0.01f; acc.z *= 0.01f; acc.w *= 0.01f;
    *(float4*)(bow + (size_t)n * KCODES + col) = acc;
}

// ---------------------------------------------------------------------------
// Kernel 5b: L1-normalize bow rows.
// ---------------------------------------------------------------------------
__global__ __launch_bounds__(256) void bow_norm_kernel(float* __restrict__ bow) {
    int n = blockIdx.x, t = threadIdx.x;
    float4* row = (float4*)(bow + (size_t)n * KCODES);
    float4 v[4];
    float s = 0.0f;
#pragma unroll
    for (int j = 0; j < 4; ++j) {
        v[j] = row[t + j * 256];
        s += fabsf(v[j].x) + fabsf(v[j].y) + fabsf(v[j].z) + fabsf(v[j].w);
    }
    __shared__ float sred[256];
    sred[t] = s;
    __syncthreads();
    for (int o = 128; o > 0; o >>= 1) {
        if (t < o) sred[t] += sred[t + o];
        __syncthreads();
    }
    float inv = 1.0f / fmaxf(sred[0], NORM_EPS);
#pragma unroll
    for (int j = 0; j < 4; ++j) {
        v[j].x *= inv; v[j].y *= inv; v[j].z *= inv; v[j].w *= inv;
        row[t + j * 256] = v[j];
    }
}

// ---------------------------------------------------------------------------
// Launch
// ---------------------------------------------------------------------------
extern "C" void kernel_launch(void* const* d_in, const int* in_sizes, int n_in,
                              void* d_out, int out_size) {
    const float* x   = (const float*)d_in[0];
    const float* emb = (const float*)d_in[1];
    float* out_bow   = (float*)d_out;
    float* out_codes = (float*)d_out + (size_t)NBATCH * KCODES;

    cudaFuncSetAttribute(gemm_exp_kernel, cudaFuncAttributeMaxDynamicSharedMemorySize,
                         SMEM_GEMM);

    prep_x_kernel<<<MROWS * 32 / 256, 256>>>(x);
    conv_emb_kernel<<<(KCODES * CDIM / 4) / 256, 256>>>(emb);

    noop_kernel<<<1, 32>>>();   // keep ncu fixed sampling slot on the GEMM

    gemm_exp_kernel<<<dim3(KCODES / BN, MROWS / BM), GTHREADS, SMEM_GEMM>>>(out_codes);

    scale_kernel<<<MROWS, 256>>>(out_codes);
    bow_partial_kernel<<<dim3(NBATCH, 16), 64>>>(out_codes, out_bow);
    bow_norm_kernel<<<NBATCH, 256>>>(out_bow);
}